// round 2
// baseline (speedup 1.0000x reference)
#include <cuda_runtime.h>
#include <math.h>

// ---- problem constants ----
#define TOK  4096      // B*Q_LEN tokens
#define HID  4096      // hidden = NH*HD
#define NHD  32        // heads
#define HDD  128       // head dim
#define NB   8         // batch sequences
#define QL   512       // query tokens per seq
#define HIS  512       // history tokens
#define BSZ  64        // paged block size
#define NBL  16        // blocks per sequence

// ---- scratch (device globals; no cudaMalloc allowed) ----
__device__ float g_q[TOK * HID];
__device__ float g_k[TOK * HID];
__device__ float g_v[TOK * HID];
__device__ float g_att[TOK * HID];

// ============================================================
// SGEMM: C[M,N] = A[M,K] @ B[K,N], row-major fp32.
// 128x128 block tile, BK=8, 256 threads, 8x8 microtile.
// ============================================================
__global__ __launch_bounds__(256) void sgemm128(const float* __restrict__ A,
                                                const float* __restrict__ B,
                                                float* __restrict__ C,
                                                int M, int N, int K)
{
    __shared__ float As[8][128];   // transposed A tile
    __shared__ float Bs[8][128];

    const int tid = threadIdx.x;
    const int row0 = blockIdx.y * 128, col0 = blockIdx.x * 128;
    const int aRow = tid >> 1, aCol = (tid & 1) * 4;
    const int bRow = tid >> 5, bCol = (tid & 31) * 4;
    const int ty = tid >> 4, tx = tid & 15;

    const float* Ap = A + (size_t)(row0 + aRow) * K + aCol;
    const float* Bp = B + (size_t)bRow * N + col0 + bCol;

    float acc[8][8];
#pragma unroll
    for (int i = 0; i < 8; i++)
#pragma unroll
        for (int j = 0; j < 8; j++) acc[i][j] = 0.f;

    for (int k0 = 0; k0 < K; k0 += 8) {
        float4 a4 = *(const float4*)Ap;
        float4 b4 = *(const float4*)Bp;
        As[aCol + 0][aRow] = a4.x; As[aCol + 1][aRow] = a4.y;
        As[aCol + 2][aRow] = a4.z; As[aCol + 3][aRow] = a4.w;
        *(float4*)&Bs[bRow][bCol] = b4;
        __syncthreads();
#pragma unroll
        for (int kk = 0; kk < 8; kk++) {
            float ra[8], rb[8];
            *(float4*)&ra[0] = *(const float4*)&As[kk][ty * 4];
            *(float4*)&ra[4] = *(const float4*)&As[kk][64 + ty * 4];
            *(float4*)&rb[0] = *(const float4*)&Bs[kk][tx * 4];
            *(float4*)&rb[4] = *(const float4*)&Bs[kk][64 + tx * 4];
#pragma unroll
            for (int i = 0; i < 8; i++)
#pragma unroll
                for (int j = 0; j < 8; j++)
                    acc[i][j] = fmaf(ra[i], rb[j], acc[i][j]);
        }
        __syncthreads();
        Ap += 8;
        Bp += (size_t)8 * N;
    }

#pragma unroll
    for (int ih = 0; ih < 2; ih++)
#pragma unroll
        for (int i = 0; i < 4; i++) {
            const int r = row0 + ih * 64 + ty * 4 + i;
            float* Cp = C + (size_t)r * N + col0;
            float4 v0 = make_float4(acc[ih*4+i][0], acc[ih*4+i][1], acc[ih*4+i][2], acc[ih*4+i][3]);
            float4 v1 = make_float4(acc[ih*4+i][4], acc[ih*4+i][5], acc[ih*4+i][6], acc[ih*4+i][7]);
            *(float4*)(Cp + tx * 4)      = v0;
            *(float4*)(Cp + 64 + tx * 4) = v1;
        }
}

// ============================================================
// RoPE (in place on g_q, g_k). Double-precision angle + range
// reduction so accuracy survives fast-math builds at pos~1023.
// ============================================================
__global__ __launch_bounds__(256) void rope_kernel(float* __restrict__ q,
                                                   float* __restrict__ k,
                                                   const int* __restrict__ pos_ids)
{
    int idx = blockIdx.x * blockDim.x + threadIdx.x;
    if (idx >= TOK * NHD * 64) return;
    const int j = idx & 63;
    const int h = (idx >> 6) & 31;
    const int t = idx >> 11;

    const double inv_freq = exp2(-(double)j / 64.0 * 13.287712379549449);  // log2(10000)
    const double ang = (double)pos_ids[t] * inv_freq;
    const double angr = remainder(ang, 6.283185307179586476925286766559);
    const float c = cosf((float)angr);
    const float s = sinf((float)angr);

    const size_t base = (size_t)t * HID + h * HDD + j;
    float q1 = q[base], q2 = q[base + 64];
    q[base]      = q1 * c - q2 * s;
    q[base + 64] = q2 * c + q1 * s;
    float k1 = k[base], k2 = k[base + 64];
    k[base]      = k1 * c - k2 * s;
    k[base + 64] = k2 * c + k1 * s;
}

// ============================================================
// Flash-style causal paged attention.
// Grid: (q_tile=8, head=32, batch=8). 256 threads/CTA.
// Q tile 64 rows, KV tile 64. Gathers history KV from the paged
// cache and new KV from g_k/g_v (scatter+gather is identity on
// new tokens, so the input caches are never modified).
// ============================================================
#define QT 64
#define KT 64
#define QSTR 132   // padded row stride (bank-conflict mitigation)
#define SSTR 68
#define ATTN_SMEM_FLOATS (3 * KT * QSTR + QT * SSTR + 3 * QT)

__global__ __launch_bounds__(256) void attn_kernel(
    const float* __restrict__ qbuf, const float* __restrict__ knew,
    const float* __restrict__ vnew, const float* __restrict__ kcache,
    const float* __restrict__ vcache, const int* __restrict__ boff,
    float* __restrict__ obuf)
{
    extern __shared__ float sm[];
    float* Qs = sm;                    // QT x QSTR
    float* Ks = Qs + QT * QSTR;        // KT x QSTR
    float* Vs = Ks + KT * QSTR;        // KT x QSTR
    float* Ss = Vs + KT * QSTR;        // QT x SSTR
    float* mrow = Ss + QT * SSTR;
    float* lrow = mrow + QT;
    float* arow = lrow + QT;

    const int qt = blockIdx.x, h = blockIdx.y, b = blockIdx.z;
    const int tid = threadIdx.x;
    const float scale = 0.08838834764831845f;   // 1/sqrt(128)

    // ---- load Q tile (scaled) ----
    for (int i = tid; i < QT * HDD / 4; i += 256) {
        int r = i >> 5;             // HDD/4 = 32 float4 per row
        int c = (i & 31) * 4;
        float4 v = *(const float4*)(qbuf + (size_t)(b * QL + qt * QT + r) * HID + h * HDD + c);
        v.x *= scale; v.y *= scale; v.z *= scale; v.w *= scale;
        *(float4*)(Qs + r * QSTR + c) = v;
    }
    if (tid < QT) { mrow[tid] = -3.0e38f; lrow[tid] = 0.f; }

    // PV ownership: rows {rg, rg+32}, cols cg*4 + u*32 + j
    const int rg = tid >> 3;
    const int cg = tid & 7;
    float o0[16], o1[16];
#pragma unroll
    for (int i = 0; i < 16; i++) { o0[i] = 0.f; o1[i] = 0.f; }

    // S ownership: rows {sr + 16i}, k-cols {kc + 16j}
    const int sr = tid >> 4;
    const int kc = tid & 15;

    __syncthreads();

    const int ntiles = 9 + qt;      // kv tiles covering [0, 512 + qt*64 + 64)
    for (int kt = 0; kt < ntiles; kt++) {
        // ---- gather K/V tile (paged cache or new tokens) ----
        for (int i = tid; i < KT * HDD / 4; i += 256) {
            int r = i >> 5;
            int c = (i & 31) * 4;
            int p = kt * KT + r;
            const float *ksrc, *vsrc;
            if (p < HIS) {
                int blk = boff[b * NBL + (p >> 6)];
                size_t base = (((size_t)blk * BSZ + (p & 63)) * NHD + h) * HDD + c;
                ksrc = kcache + base; vsrc = vcache + base;
            } else {
                size_t base = (size_t)(b * QL + (p - HIS)) * HID + h * HDD + c;
                ksrc = knew + base; vsrc = vnew + base;
            }
            *(float4*)(Ks + r * QSTR + c) = *(const float4*)ksrc;
            *(float4*)(Vs + r * QSTR + c) = *(const float4*)vsrc;
        }
        __syncthreads();

        // ---- scores S = Q K^T (4x4 microtile per thread) ----
        {
            float acc[4][4];
#pragma unroll
            for (int i = 0; i < 4; i++)
#pragma unroll
                for (int j = 0; j < 4; j++) acc[i][j] = 0.f;

            for (int d = 0; d < HDD; d += 4) {
                float4 q4[4], k4[4];
#pragma unroll
                for (int i = 0; i < 4; i++) q4[i] = *(const float4*)(Qs + (sr + 16 * i) * QSTR + d);
#pragma unroll
                for (int j = 0; j < 4; j++) k4[j] = *(const float4*)(Ks + (kc + 16 * j) * QSTR + d);
#pragma unroll
                for (int i = 0; i < 4; i++)
#pragma unroll
                    for (int j = 0; j < 4; j++)
                        acc[i][j] += q4[i].x * k4[j].x + q4[i].y * k4[j].y
                                   + q4[i].z * k4[j].z + q4[i].w * k4[j].w;
            }
#pragma unroll
            for (int i = 0; i < 4; i++)
#pragma unroll
                for (int j = 0; j < 4; j++)
                    Ss[(sr + 16 * i) * SSTR + kc + 16 * j] = acc[i][j];
        }
        __syncthreads();

        // ---- online softmax update (one thread per row) ----
        if (tid < QT) {
            const int r = tid;
            const int qpos = HIS + qt * QT + r;
            int kmax = qpos - kt * KT + 1;        // causal: p <= qpos
            if (kmax > KT) kmax = KT;
            float m_old = mrow[r];
            float m = m_old;
            for (int k = 0; k < kmax; k++) m = fmaxf(m, Ss[r * SSTR + k]);
            float alpha = __expf(m_old - m);
            float l = lrow[r] * alpha;
            for (int k = 0; k < kmax; k++) {
                float p = __expf(Ss[r * SSTR + k] - m);
                Ss[r * SSTR + k] = p;
                l += p;
            }
            for (int k = kmax; k < KT; k++) Ss[r * SSTR + k] = 0.f;
            mrow[r] = m; lrow[r] = l; arow[r] = alpha;
        }
        __syncthreads();

        // ---- rescale old accumulators + P @ V ----
        {
            const float aA = arow[rg], aB = arow[rg + 32];
#pragma unroll
            for (int i = 0; i < 16; i++) { o0[i] *= aA; o1[i] *= aB; }
            const float* pa = Ss + rg * SSTR;
            const float* pb = Ss + (rg + 32) * SSTR;
            for (int k = 0; k < KT; k++) {
                float p0 = pa[k], p1 = pb[k];
                const float* vrow = Vs + k * QSTR + cg * 4;
#pragma unroll
                for (int u = 0; u < 4; u++) {
                    float4 v4 = *(const float4*)(vrow + u * 32);
                    o0[u*4+0] = fmaf(p0, v4.x, o0[u*4+0]);
                    o0[u*4+1] = fmaf(p0, v4.y, o0[u*4+1]);
                    o0[u*4+2] = fmaf(p0, v4.z, o0[u*4+2]);
                    o0[u*4+3] = fmaf(p0, v4.w, o0[u*4+3]);
                    o1[u*4+0] = fmaf(p1, v4.x, o1[u*4+0]);
                    o1[u*4+1] = fmaf(p1, v4.y, o1[u*4+1]);
                    o1[u*4+2] = fmaf(p1, v4.z, o1[u*4+2]);
                    o1[u*4+3] = fmaf(p1, v4.w, o1[u*4+3]);
                }
            }
        }
        __syncthreads();
    }

    // ---- normalize + write out ----
    const float inv0 = 1.f / lrow[rg];
    const float inv1 = 1.f / lrow[rg + 32];
    const int t0 = b * QL + qt * QT;
    float* oA = obuf + (size_t)(t0 + rg) * HID + h * HDD + cg * 4;
    float* oB = obuf + (size_t)(t0 + rg + 32) * HID + h * HDD + cg * 4;
#pragma unroll
    for (int u = 0; u < 4; u++) {
        float4 a = make_float4(o0[u*4]*inv0, o0[u*4+1]*inv0, o0[u*4+2]*inv0, o0[u*4+3]*inv0);
        float4 c = make_float4(o1[u*4]*inv1, o1[u*4+1]*inv1, o1[u*4+2]*inv1, o1[u*4+3]*inv1);
        *(float4*)(oA + u * 32) = a;
        *(float4*)(oB + u * 32) = c;
    }
}

// ============================================================
// launch
// ============================================================
extern "C" void kernel_launch(void* const* d_in, const int* in_sizes, int n_in,
                              void* d_out, int out_size)
{
    const float* hidden = (const float*)d_in[0];
    const float* Wq     = (const float*)d_in[1];
    const float* Wk     = (const float*)d_in[2];
    const float* Wv     = (const float*)d_in[3];
    const float* Wo     = (const float*)d_in[4];
    const float* kcache = (const float*)d_in[5];
    const float* vcache = (const float*)d_in[6];
    const int*   boff   = (const int*)d_in[7];
    const int*   pos    = (const int*)d_in[8];
    float* out = (float*)d_out;

    float *gq, *gk, *gv, *ga;
    cudaGetSymbolAddress((void**)&gq, g_q);
    cudaGetSymbolAddress((void**)&gk, g_k);
    cudaGetSymbolAddress((void**)&gv, g_v);
    cudaGetSymbolAddress((void**)&ga, g_att);

    // QKV projections
    dim3 gg(HID / 128, TOK / 128);
    sgemm128<<<gg, 256>>>(hidden, Wq, gq, TOK, HID, HID);
    sgemm128<<<gg, 256>>>(hidden, Wk, gk, TOK, HID, HID);
    sgemm128<<<gg, 256>>>(hidden, Wv, gv, TOK, HID, HID);

    // RoPE on q, k
    rope_kernel<<<(TOK * NHD * 64 + 255) / 256, 256>>>(gq, gk, pos);

    // attention
    const int smem_bytes = ATTN_SMEM_FLOATS * (int)sizeof(float);
    cudaFuncSetAttribute(attn_kernel, cudaFuncAttributeMaxDynamicSharedMemorySize, smem_bytes);
    dim3 ag(QL / QT, NHD, NB);
    attn_kernel<<<ag, 256, smem_bytes>>>(gq, gk, gv, kcache, vcache, boff, ga);

    // output projection
    sgemm128<<<gg, 256>>>(ga, Wo, out, TOK, HID, HID);
}

// round 4
// speedup vs baseline: 2.1970x; 2.1970x over previous
#include <cuda_runtime.h>
#include <cuda_bf16.h>
#include <math.h>
#include <stdint.h>

// ---- problem constants ----
#define TOK  4096
#define HID  4096
#define NHD  32
#define HDD  128
#define NB   8
#define QL   512
#define HIS  512
#define BSZ  64
#define NBL  16

// ---- scratch (device globals; no cudaMalloc allowed) ----
__device__ float g_q[TOK * HID];
__device__ float g_k[TOK * HID];
__device__ float g_v[TOK * HID];
__device__ float g_att[TOK * HID];
__device__ __nv_bfloat16 g_Ahi[TOK * HID];
__device__ __nv_bfloat16 g_Alo[TOK * HID];
__device__ __nv_bfloat16 g_Wthi[4][HID * HID];  // transposed weights [N,K]
__device__ __nv_bfloat16 g_Wtlo[4][HID * HID];

// ============================================================
// helpers
// ============================================================
__device__ __forceinline__ uint32_t smem_u32(const void* p) {
    uint32_t a;
    asm("{ .reg .u64 t; cvta.to.shared.u64 t, %1; cvt.u32.u64 %0, t; }" : "=r"(a) : "l"(p));
    return a;
}
__device__ __forceinline__ void cp16(uint32_t dst, const void* src) {
    asm volatile("cp.async.cg.shared.global [%0], [%1], 16;" :: "r"(dst), "l"(src));
}
__device__ __forceinline__ void cp_commit() {
    asm volatile("cp.async.commit_group;" ::: "memory");
}
template <int N> __device__ __forceinline__ void cp_wait() {
    asm volatile("cp.async.wait_group %0;" :: "n"(N) : "memory");
}
__device__ __forceinline__ void ldm4(uint32_t* r, uint32_t addr) {
    asm volatile("ldmatrix.sync.aligned.m8n8.x4.shared.b16 {%0,%1,%2,%3}, [%4];"
                 : "=r"(r[0]), "=r"(r[1]), "=r"(r[2]), "=r"(r[3]) : "r"(addr));
}
__device__ __forceinline__ void mma16816(float* d, const uint32_t* a, const uint32_t* b) {
    asm volatile(
        "mma.sync.aligned.m16n8k16.row.col.f32.bf16.bf16.f32 "
        "{%0,%1,%2,%3}, {%4,%5,%6,%7}, {%8,%9}, {%0,%1,%2,%3};"
        : "+f"(d[0]), "+f"(d[1]), "+f"(d[2]), "+f"(d[3])
        : "r"(a[0]), "r"(a[1]), "r"(a[2]), "r"(a[3]), "r"(b[0]), "r"(b[1]));
}

// ============================================================
// Split fp32 -> bf16 hi/lo
// ============================================================
__global__ __launch_bounds__(256) void split_kernel(const float4* __restrict__ src,
                                                    __nv_bfloat16* __restrict__ hi,
                                                    __nv_bfloat16* __restrict__ lo)
{
    int i = blockIdx.x * 256 + threadIdx.x;
    float4 v = src[i];
    __nv_bfloat16 h0 = __float2bfloat16(v.x), h1 = __float2bfloat16(v.y);
    __nv_bfloat16 h2 = __float2bfloat16(v.z), h3 = __float2bfloat16(v.w);
    __nv_bfloat16 l0 = __float2bfloat16(v.x - __bfloat162float(h0));
    __nv_bfloat16 l1 = __float2bfloat16(v.y - __bfloat162float(h1));
    __nv_bfloat16 l2 = __float2bfloat16(v.z - __bfloat162float(h2));
    __nv_bfloat16 l3 = __float2bfloat16(v.w - __bfloat162float(h3));
    __nv_bfloat162* hp = (__nv_bfloat162*)hi;
    __nv_bfloat162* lp = (__nv_bfloat162*)lo;
    hp[i * 2]     = __nv_bfloat162(h0, h1);
    hp[i * 2 + 1] = __nv_bfloat162(h2, h3);
    lp[i * 2]     = __nv_bfloat162(l0, l1);
    lp[i * 2 + 1] = __nv_bfloat162(l2, l3);
}

// ============================================================
// Transpose W[K,N] fp32 -> Wt[N,K] bf16 hi/lo
// ============================================================
__global__ __launch_bounds__(256) void transpose_split(const float* __restrict__ W,
                                                       __nv_bfloat16* __restrict__ hi,
                                                       __nv_bfloat16* __restrict__ lo)
{
    __shared__ float tile[32][33];
    const int bx = blockIdx.x, by = blockIdx.y;
    const int tx = threadIdx.x & 31, ty = threadIdx.x >> 5;
#pragma unroll
    for (int j = 0; j < 4; j++)
        tile[ty + j * 8][tx] = W[(size_t)(by * 32 + ty + j * 8) * HID + bx * 32 + tx];
    __syncthreads();
#pragma unroll
    for (int j = 0; j < 4; j++) {
        float v = tile[tx][ty + j * 8];
        __nv_bfloat16 h = __float2bfloat16(v);
        __nv_bfloat16 l = __float2bfloat16(v - __bfloat162float(h));
        size_t o = (size_t)(bx * 32 + ty + j * 8) * HID + by * 32 + tx;
        hi[o] = h; lo[o] = l;
    }
}

// ============================================================
// HMMA bf16-split GEMM: C[4096,4096] = A @ Bt^T
// A (hi/lo): [M,K] row-major bf16. Bt (hi/lo): [N,K] row-major.
// CTA tile 128x128, BK=32, 3-stage cp.async, warp tile 64x32.
// Smem rows at stride 80B -> conflict-free ldmatrix (granule (5r+c)%8).
// ============================================================
#define ROWB   80
#define TILEB  (128 * ROWB)          // 10240 B per (128 x 32bf16) tile
#define STAGEB (4 * TILEB)           // Ahi, Alo, Bhi, Blo
#define GEMM_SMEM (3 * STAGEB)       // 122880 B

__global__ __launch_bounds__(256, 1) void gemm_mma(const __nv_bfloat16* __restrict__ Ahi,
                                                   const __nv_bfloat16* __restrict__ Alo,
                                                   const __nv_bfloat16* __restrict__ Bhi,
                                                   const __nv_bfloat16* __restrict__ Blo,
                                                   float* __restrict__ C)
{
    extern __shared__ char smem[];
    const uint32_t sbase = smem_u32(smem);
    const int tid = threadIdx.x;
    const int lane = tid & 31, wid = tid >> 5;
    const int wm = wid & 1, wn = wid >> 1;          // warp grid 2(M) x 4(N)
    const int row0 = blockIdx.y * 128, col0 = blockIdx.x * 128;

    const __nv_bfloat16* tsrc[4] = {
        Ahi + (size_t)row0 * HID, Alo + (size_t)row0 * HID,
        Bhi + (size_t)col0 * HID, Blo + (size_t)col0 * HID };

    // fill chunk mapping: 2048 chunks of 16B; id = tid + i*256
    // tile = id>>9, r = (id>>2)&127, c = id&3
    auto fill = [&](int stage, int kblk) {
        const uint32_t sb = sbase + stage * STAGEB;
        const int koff = kblk * 32;
#pragma unroll
        for (int i = 0; i < 8; i++) {
            int id = tid + i * 256;
            int t = id >> 9;
            int r = (id >> 2) & 127;
            int c = id & 3;
            cp16(sb + t * TILEB + r * ROWB + c * 16,
                 tsrc[t] + (size_t)r * HID + koff + c * 8);
        }
        cp_commit();
    };

    float acc[4][4][4];
#pragma unroll
    for (int i = 0; i < 4; i++)
#pragma unroll
        for (int j = 0; j < 4; j++)
#pragma unroll
            for (int u = 0; u < 4; u++) acc[i][j][u] = 0.f;

    fill(0, 0); fill(1, 1); fill(2, 2);

    // ldmatrix lane addressing (byte offsets within tile)
    const int a_row = (lane & 15);
    const int a_cb  = (lane >> 4) * 16;
    const int b_row = (lane & 7) + ((lane >> 4) << 3);
    const int b_cb  = ((lane >> 3) & 1) * 16;

    const int NKB = HID / 32;   // 128 k-blocks
    for (int c = 0; c < NKB; ++c) {
        const int s = c % 3;
        cp_wait<2>();
        __syncthreads();
        const uint32_t sb = sbase + s * STAGEB;
        const uint32_t aAh = sb + (wm * 64 + a_row) * ROWB + a_cb;
        const uint32_t aAl = aAh + TILEB;
        const uint32_t aBh = sb + 2 * TILEB + (wn * 32 + b_row) * ROWB + b_cb;
        const uint32_t aBl = aBh + TILEB;

#pragma unroll
        for (int ks = 0; ks < 2; ++ks) {
            const int kb = ks * 32;
            uint32_t ah[4][4], al[4][4], bh[2][4], bl[2][4];
#pragma unroll
            for (int i = 0; i < 4; i++) {
                ldm4(ah[i], aAh + i * (16 * ROWB) + kb);
                ldm4(al[i], aAl + i * (16 * ROWB) + kb);
            }
#pragma unroll
            for (int j = 0; j < 2; j++) {
                ldm4(bh[j], aBh + j * (16 * ROWB) + kb);
                ldm4(bl[j], aBl + j * (16 * ROWB) + kb);
            }
#pragma unroll
            for (int i = 0; i < 4; i++)
#pragma unroll
                for (int j = 0; j < 4; j++) {
                    const uint32_t* bhp = &bh[j >> 1][(j & 1) * 2];
                    const uint32_t* blp = &bl[j >> 1][(j & 1) * 2];
                    mma16816(acc[i][j], ah[i], bhp);
                    mma16816(acc[i][j], ah[i], blp);
                    mma16816(acc[i][j], al[i], bhp);
                }
        }
        __syncthreads();
        if (c + 3 < NKB) fill(s, c + 3);
        else cp_commit();
    }

    // epilogue
    const int erow = row0 + wm * 64 + (lane >> 2);
    const int ecol = col0 + wn * 32 + (lane & 3) * 2;
#pragma unroll
    for (int i = 0; i < 4; i++)
#pragma unroll
        for (int j = 0; j < 4; j++) {
            float* p0 = C + (size_t)(erow + i * 16) * HID + ecol + j * 8;
            float* p1 = C + (size_t)(erow + i * 16 + 8) * HID + ecol + j * 8;
            *(float2*)p0 = make_float2(acc[i][j][0], acc[i][j][1]);
            *(float2*)p1 = make_float2(acc[i][j][2], acc[i][j][3]);
        }
}

// ============================================================
// RoPE: one thread per (token, j<64); loops over 32 heads.
// ============================================================
__global__ __launch_bounds__(256) void rope_kernel2(float* __restrict__ q,
                                                    float* __restrict__ k,
                                                    const int* __restrict__ pos)
{
    const int idx = blockIdx.x * 256 + threadIdx.x;
    const int j = idx & 63, t = idx >> 6;
    const double inv_freq = exp2(-(double)j * (13.287712379549449 / 64.0));
    const double ang = (double)pos[t] * inv_freq;
    const float a = (float)remainder(ang, 6.283185307179586476925286766559);
    const float c = cosf(a), s = sinf(a);
    const size_t base = (size_t)t * HID + j;
#pragma unroll 4
    for (int h = 0; h < 32; ++h) {
        const size_t o = base + h * HDD;
        float q1 = q[o], q2 = q[o + 64];
        q[o]      = q1 * c - q2 * s;
        q[o + 64] = q2 * c + q1 * s;
        float k1 = k[o], k2 = k[o + 64];
        k[o]      = k1 * c - k2 * s;
        k[o + 64] = k2 * c + k1 * s;
    }
}

// ============================================================
// Flash-style causal paged attention (unchanged, fp32)
// ============================================================
#define QT 64
#define KT 64
#define QSTR 132
#define SSTR 68
#define ATTN_SMEM_FLOATS (3 * KT * QSTR + QT * SSTR + 3 * QT)

__global__ __launch_bounds__(256) void attn_kernel(
    const float* __restrict__ qbuf, const float* __restrict__ knew,
    const float* __restrict__ vnew, const float* __restrict__ kcache,
    const float* __restrict__ vcache, const int* __restrict__ boff,
    float* __restrict__ obuf)
{
    extern __shared__ float sm[];
    float* Qs = sm;
    float* Ks = Qs + QT * QSTR;
    float* Vs = Ks + KT * QSTR;
    float* Ss = Vs + KT * QSTR;
    float* mrow = Ss + QT * SSTR;
    float* lrow = mrow + QT;
    float* arow = lrow + QT;

    const int qt = blockIdx.x, h = blockIdx.y, b = blockIdx.z;
    const int tid = threadIdx.x;
    const float scale = 0.08838834764831845f;

    for (int i = tid; i < QT * HDD / 4; i += 256) {
        int r = i >> 5;
        int c = (i & 31) * 4;
        float4 v = *(const float4*)(qbuf + (size_t)(b * QL + qt * QT + r) * HID + h * HDD + c);
        v.x *= scale; v.y *= scale; v.z *= scale; v.w *= scale;
        *(float4*)(Qs + r * QSTR + c) = v;
    }
    if (tid < QT) { mrow[tid] = -3.0e38f; lrow[tid] = 0.f; }

    const int rg = tid >> 3;
    const int cg = tid & 7;
    float o0[16], o1[16];
#pragma unroll
    for (int i = 0; i < 16; i++) { o0[i] = 0.f; o1[i] = 0.f; }

    const int sr = tid >> 4;
    const int kc = tid & 15;

    __syncthreads();

    const int ntiles = 9 + qt;
    for (int kt = 0; kt < ntiles; kt++) {
        for (int i = tid; i < KT * HDD / 4; i += 256) {
            int r = i >> 5;
            int c = (i & 31) * 4;
            int p = kt * KT + r;
            const float *ksrc, *vsrc;
            if (p < HIS) {
                int blk = boff[b * NBL + (p >> 6)];
                size_t base = (((size_t)blk * BSZ + (p & 63)) * NHD + h) * HDD + c;
                ksrc = kcache + base; vsrc = vcache + base;
            } else {
                size_t base = (size_t)(b * QL + (p - HIS)) * HID + h * HDD + c;
                ksrc = knew + base; vsrc = vnew + base;
            }
            *(float4*)(Ks + r * QSTR + c) = *(const float4*)ksrc;
            *(float4*)(Vs + r * QSTR + c) = *(const float4*)vsrc;
        }
        __syncthreads();

        {
            float a4[4][4];
#pragma unroll
            for (int i = 0; i < 4; i++)
#pragma unroll
                for (int j = 0; j < 4; j++) a4[i][j] = 0.f;

            for (int d = 0; d < HDD; d += 4) {
                float4 q4[4], k4[4];
#pragma unroll
                for (int i = 0; i < 4; i++) q4[i] = *(const float4*)(Qs + (sr + 16 * i) * QSTR + d);
#pragma unroll
                for (int j = 0; j < 4; j++) k4[j] = *(const float4*)(Ks + (kc + 16 * j) * QSTR + d);
#pragma unroll
                for (int i = 0; i < 4; i++)
#pragma unroll
                    for (int j = 0; j < 4; j++)
                        a4[i][j] += q4[i].x * k4[j].x + q4[i].y * k4[j].y
                                  + q4[i].z * k4[j].z + q4[i].w * k4[j].w;
            }
#pragma unroll
            for (int i = 0; i < 4; i++)
#pragma unroll
                for (int j = 0; j < 4; j++)
                    Ss[(sr + 16 * i) * SSTR + kc + 16 * j] = a4[i][j];
        }
        __syncthreads();

        if (tid < QT) {
            const int r = tid;
            const int qpos = HIS + qt * QT + r;
            int kmax = qpos - kt * KT + 1;
            if (kmax > KT) kmax = KT;
            float m_old = mrow[r];
            float m = m_old;
            for (int k = 0; k < kmax; k++) m = fmaxf(m, Ss[r * SSTR + k]);
            float alpha = __expf(m_old - m);
            float l = lrow[r] * alpha;
            for (int k = 0; k < kmax; k++) {
                float p = __expf(Ss[r * SSTR + k] - m);
                Ss[r * SSTR + k] = p;
                l += p;
            }
            for (int k = kmax; k < KT; k++) Ss[r * SSTR + k] = 0.f;
            mrow[r] = m; lrow[r] = l; arow[r] = alpha;
        }
        __syncthreads();

        {
            const float aA = arow[rg], aB = arow[rg + 32];
#pragma unroll
            for (int i = 0; i < 16; i++) { o0[i] *= aA; o1[i] *= aB; }
            const float* pa = Ss + rg * SSTR;
            const float* pb = Ss + (rg + 32) * SSTR;
            for (int k = 0; k < KT; k++) {
                float p0 = pa[k], p1 = pb[k];
                const float* vrow = Vs + k * QSTR + cg * 4;
#pragma unroll
                for (int u = 0; u < 4; u++) {
                    float4 v4 = *(const float4*)(vrow + u * 32);
                    o0[u*4+0] = fmaf(p0, v4.x, o0[u*4+0]);
                    o0[u*4+1] = fmaf(p0, v4.y, o0[u*4+1]);
                    o0[u*4+2] = fmaf(p0, v4.z, o0[u*4+2]);
                    o0[u*4+3] = fmaf(p0, v4.w, o0[u*4+3]);
                    o1[u*4+0] = fmaf(p1, v4.x, o1[u*4+0]);
                    o1[u*4+1] = fmaf(p1, v4.y, o1[u*4+1]);
                    o1[u*4+2] = fmaf(p1, v4.z, o1[u*4+2]);
                    o1[u*4+3] = fmaf(p1, v4.w, o1[u*4+3]);
                }
            }
        }
        __syncthreads();
    }

    const float inv0 = 1.f / lrow[rg];
    const float inv1 = 1.f / lrow[rg + 32];
    const int t0 = b * QL + qt * QT;
    float* oA = obuf + (size_t)(t0 + rg) * HID + h * HDD + cg * 4;
    float* oB = obuf + (size_t)(t0 + rg + 32) * HID + h * HDD + cg * 4;
#pragma unroll
    for (int u = 0; u < 4; u++) {
        float4 a = make_float4(o0[u*4]*inv0, o0[u*4+1]*inv0, o0[u*4+2]*inv0, o0[u*4+3]*inv0);
        float4 c = make_float4(o1[u*4]*inv1, o1[u*4+1]*inv1, o1[u*4+2]*inv1, o1[u*4+3]*inv1);
        *(float4*)(oA + u * 32) = a;
        *(float4*)(oB + u * 32) = c;
    }
}

// ============================================================
// launch
// ============================================================
extern "C" void kernel_launch(void* const* d_in, const int* in_sizes, int n_in,
                              void* d_out, int out_size)
{
    const float* hidden = (const float*)d_in[0];
    const float* Wq     = (const float*)d_in[1];
    const float* Wk     = (const float*)d_in[2];
    const float* Wv     = (const float*)d_in[3];
    const float* Wo     = (const float*)d_in[4];
    const float* kcache = (const float*)d_in[5];
    const float* vcache = (const float*)d_in[6];
    const int*   boff   = (const int*)d_in[7];
    const int*   pos    = (const int*)d_in[8];
    float* out = (float*)d_out;

    float *gq, *gk, *gv, *ga;
    __nv_bfloat16 *ahi, *alo, *whi, *wlo;
    cudaGetSymbolAddress((void**)&gq, g_q);
    cudaGetSymbolAddress((void**)&gk, g_k);
    cudaGetSymbolAddress((void**)&gv, g_v);
    cudaGetSymbolAddress((void**)&ga, g_att);
    cudaGetSymbolAddress((void**)&ahi, g_Ahi);
    cudaGetSymbolAddress((void**)&alo, g_Alo);
    cudaGetSymbolAddress((void**)&whi, g_Wthi);
    cudaGetSymbolAddress((void**)&wlo, g_Wtlo);

    cudaFuncSetAttribute(gemm_mma, cudaFuncAttributeMaxDynamicSharedMemorySize, GEMM_SMEM);
    cudaFuncSetAttribute(attn_kernel, cudaFuncAttributeMaxDynamicSharedMemorySize,
                         ATTN_SMEM_FLOATS * (int)sizeof(float));

    const int nsplit = TOK * HID / 4 / 256;
    dim3 tgrid(HID / 32, HID / 32);
    dim3 ggrid(HID / 128, TOK / 128);

    split_kernel<<<nsplit, 256>>>((const float4*)hidden, ahi, alo);
    transpose_split<<<tgrid, 256>>>(Wq, whi + 0 * (size_t)HID * HID, wlo + 0 * (size_t)HID * HID);
    transpose_split<<<tgrid, 256>>>(Wk, whi + 1 * (size_t)HID * HID, wlo + 1 * (size_t)HID * HID);
    transpose_split<<<tgrid, 256>>>(Wv, whi + 2 * (size_t)HID * HID, wlo + 2 * (size_t)HID * HID);
    transpose_split<<<tgrid, 256>>>(Wo, whi + 3 * (size_t)HID * HID, wlo + 3 * (size_t)HID * HID);

    gemm_mma<<<ggrid, 256, GEMM_SMEM>>>(ahi, alo, whi + 0 * (size_t)HID * HID, wlo + 0 * (size_t)HID * HID, gq);
    gemm_mma<<<ggrid, 256, GEMM_SMEM>>>(ahi, alo, whi + 1 * (size_t)HID * HID, wlo + 1 * (size_t)HID * HID, gk);
    gemm_mma<<<ggrid, 256, GEMM_SMEM>>>(ahi, alo, whi + 2 * (size_t)HID * HID, wlo + 2 * (size_t)HID * HID, gv);

    rope_kernel2<<<TOK * 64 / 256, 256>>>(gq, gk, pos);

    dim3 ag(QL / QT, NHD, NB);
    attn_kernel<<<ag, 256, ATTN_SMEM_FLOATS * (int)sizeof(float)>>>(gq, gk, gv, kcache, vcache, boff, ga);

    split_kernel<<<nsplit, 256>>>((const float4*)ga, ahi, alo);
    gemm_mma<<<ggrid, 256, GEMM_SMEM>>>(ahi, alo, whi + 3 * (size_t)HID * HID, wlo + 3 * (size_t)HID * HID, out);
}

// round 5
// speedup vs baseline: 6.3435x; 2.8874x over previous
#include <cuda_runtime.h>
#include <cuda_fp16.h>
#include <math.h>
#include <stdint.h>

// ---- problem constants ----
#define TOK  4096
#define HID  4096
#define NHD  32
#define HDD  128
#define NB   8
#define QL   512
#define HIS  512
#define BSZ  64
#define NBL  16

// ---- scratch ----
__device__ float g_q[TOK * HID];
__device__ float g_k[TOK * HID];
__device__ float g_v[TOK * HID];
__device__ float g_att[TOK * HID];
__device__ __half g_Ah[TOK * HID];
__device__ __half g_Wt[4][HID * HID];   // transposed weights [N,K] fp16

// ============================================================
// helpers
// ============================================================
__device__ __forceinline__ uint32_t smem_u32(const void* p) {
    uint32_t a;
    asm("{ .reg .u64 t; cvta.to.shared.u64 t, %1; cvt.u32.u64 %0, t; }" : "=r"(a) : "l"(p));
    return a;
}
__device__ __forceinline__ void cp16(uint32_t dst, const void* src) {
    asm volatile("cp.async.cg.shared.global [%0], [%1], 16;" :: "r"(dst), "l"(src));
}
__device__ __forceinline__ void cp_commit() {
    asm volatile("cp.async.commit_group;" ::: "memory");
}
template <int N> __device__ __forceinline__ void cp_wait() {
    asm volatile("cp.async.wait_group %0;" :: "n"(N) : "memory");
}
__device__ __forceinline__ void ldm4(uint32_t* r, uint32_t addr) {
    asm volatile("ldmatrix.sync.aligned.m8n8.x4.shared.b16 {%0,%1,%2,%3}, [%4];"
                 : "=r"(r[0]), "=r"(r[1]), "=r"(r[2]), "=r"(r[3]) : "r"(addr));
}
__device__ __forceinline__ void ldm4t(uint32_t* r, uint32_t addr) {
    asm volatile("ldmatrix.sync.aligned.m8n8.x4.trans.shared.b16 {%0,%1,%2,%3}, [%4];"
                 : "=r"(r[0]), "=r"(r[1]), "=r"(r[2]), "=r"(r[3]) : "r"(addr));
}
__device__ __forceinline__ void mmah(float* d, const uint32_t* a, const uint32_t* b) {
    asm volatile(
        "mma.sync.aligned.m16n8k16.row.col.f32.f16.f16.f32 "
        "{%0,%1,%2,%3}, {%4,%5,%6,%7}, {%8,%9}, {%0,%1,%2,%3};"
        : "+f"(d[0]), "+f"(d[1]), "+f"(d[2]), "+f"(d[3])
        : "r"(a[0]), "r"(a[1]), "r"(a[2]), "r"(a[3]), "r"(b[0]), "r"(b[1]));
}
__device__ __forceinline__ uint32_t packh2(float x, float y) {
    __half2 h = __floats2half2_rn(x, y);
    return *reinterpret_cast<uint32_t*>(&h);
}
// fast exp on FMA pipe (x <= ~0, |err| ~2e-6 rel); avoids MUFU bottleneck
__device__ __forceinline__ float fexp(float x) {
    float t = fmaxf(x * 1.4426950408889634f, -80.0f);
    int   i = __float2int_rn(t);
    float f = t - (float)i;                 // f in [-0.5, 0.5]
    float p = 0.0013333558f;
    p = fmaf(p, f, 0.0096181291f);
    p = fmaf(p, f, 0.0555041087f);
    p = fmaf(p, f, 0.2402265069f);
    p = fmaf(p, f, 0.6931471806f);
    p = fmaf(p, f, 1.0f);
    return p * __int_as_float((i + 127) << 23);
}

// ============================================================
// fp32 -> fp16 convert (vectorized)
// ============================================================
__global__ __launch_bounds__(256) void cvt_half(const float4* __restrict__ src,
                                                __half* __restrict__ dst)
{
    int i = blockIdx.x * 256 + threadIdx.x;
    float4 v = src[i];
    __half2* d = (__half2*)dst;
    d[i * 2]     = __floats2half2_rn(v.x, v.y);
    d[i * 2 + 1] = __floats2half2_rn(v.z, v.w);
}

// ============================================================
// Transpose W[K,N] fp32 -> Wt[N,K] fp16
// ============================================================
__global__ __launch_bounds__(256) void transpose_half(const float* __restrict__ W,
                                                      __half* __restrict__ dst)
{
    __shared__ float tile[32][33];
    const int bx = blockIdx.x, by = blockIdx.y;
    const int tx = threadIdx.x & 31, ty = threadIdx.x >> 5;
#pragma unroll
    for (int j = 0; j < 4; j++)
        tile[ty + j * 8][tx] = W[(size_t)(by * 32 + ty + j * 8) * HID + bx * 32 + tx];
    __syncthreads();
#pragma unroll
    for (int j = 0; j < 4; j++) {
        float v = tile[tx][ty + j * 8];
        dst[(size_t)(bx * 32 + ty + j * 8) * HID + by * 32 + tx] = __float2half(v);
    }
}

// ============================================================
// fp16 HMMA GEMM: C[4096,4096] = A @ Bt^T  (fp32 accumulate)
// CTA 128x128, BK=32, 3-stage cp.async, warp tile 64x32.
// ============================================================
#define ROWB   80
#define TILEB  (128 * ROWB)
#define STAGEB (2 * TILEB)
#define GEMM_SMEM (3 * STAGEB)   // 61440

__global__ __launch_bounds__(256, 2) void gemm_fp16(const __half* __restrict__ A,
                                                    const __half* __restrict__ B,
                                                    float* __restrict__ C)
{
    extern __shared__ char smem[];
    const uint32_t sbase = smem_u32(smem);
    const int tid = threadIdx.x;
    const int lane = tid & 31, wid = tid >> 5;
    const int wm = wid & 1, wn = wid >> 1;
    const int row0 = blockIdx.y * 128, col0 = blockIdx.x * 128;

    const __half* tsrc[2] = { A + (size_t)row0 * HID, B + (size_t)col0 * HID };

    auto fill = [&](int stage, int kblk) {
        const uint32_t sb = sbase + stage * STAGEB;
        const int koff = kblk * 32;
#pragma unroll
        for (int i = 0; i < 4; i++) {
            int id = tid + i * 256;
            int t = id >> 9;
            int r = (id >> 2) & 127;
            int c = id & 3;
            cp16(sb + t * TILEB + r * ROWB + c * 16,
                 tsrc[t] + (size_t)r * HID + koff + c * 8);
        }
        cp_commit();
    };

    float acc[4][4][4];
#pragma unroll
    for (int i = 0; i < 4; i++)
#pragma unroll
        for (int j = 0; j < 4; j++)
#pragma unroll
            for (int u = 0; u < 4; u++) acc[i][j][u] = 0.f;

    fill(0, 0); fill(1, 1); fill(2, 2);

    const int a_row = (lane & 15);
    const int a_cb  = (lane >> 4) * 16;
    const int b_row = (lane & 7) + ((lane >> 4) << 3);
    const int b_cb  = ((lane >> 3) & 1) * 16;

    const int NKB = HID / 32;
    for (int c = 0; c < NKB; ++c) {
        const int s = c % 3;
        cp_wait<2>();
        __syncthreads();
        const uint32_t sb = sbase + s * STAGEB;
        const uint32_t aA = sb + (wm * 64 + a_row) * ROWB + a_cb;
        const uint32_t aB = sb + TILEB + (wn * 32 + b_row) * ROWB + b_cb;

#pragma unroll
        for (int ks = 0; ks < 2; ++ks) {
            const int kb = ks * 32;
            uint32_t a[4][4], b[2][4];
#pragma unroll
            for (int i = 0; i < 4; i++) ldm4(a[i], aA + i * (16 * ROWB) + kb);
#pragma unroll
            for (int j = 0; j < 2; j++) ldm4(b[j], aB + j * (16 * ROWB) + kb);
#pragma unroll
            for (int i = 0; i < 4; i++)
#pragma unroll
                for (int j = 0; j < 4; j++)
                    mmah(acc[i][j], a[i], &b[j >> 1][(j & 1) * 2]);
        }
        __syncthreads();
        if (c + 3 < NKB) fill(s, c + 3);
        else cp_commit();
    }

    const int erow = row0 + wm * 64 + (lane >> 2);
    const int ecol = col0 + wn * 32 + (lane & 3) * 2;
#pragma unroll
    for (int i = 0; i < 4; i++)
#pragma unroll
        for (int j = 0; j < 4; j++) {
            float* p0 = C + (size_t)(erow + i * 16) * HID + ecol + j * 8;
            float* p1 = C + (size_t)(erow + i * 16 + 8) * HID + ecol + j * 8;
            *(float2*)p0 = make_float2(acc[i][j][0], acc[i][j][1]);
            *(float2*)p1 = make_float2(acc[i][j][2], acc[i][j][3]);
        }
}

// ============================================================
// RoPE
// ============================================================
__global__ __launch_bounds__(256) void rope_kernel2(float* __restrict__ q,
                                                    float* __restrict__ k,
                                                    const int* __restrict__ pos)
{
    const int idx = blockIdx.x * 256 + threadIdx.x;
    const int j = idx & 63, t = idx >> 6;
    const double inv_freq = exp2(-(double)j * (13.287712379549449 / 64.0));
    const double ang = (double)pos[t] * inv_freq;
    const float a = (float)remainder(ang, 6.283185307179586476925286766559);
    const float c = cosf(a), s = sinf(a);
    const size_t base = (size_t)t * HID + j;
#pragma unroll 4
    for (int h = 0; h < 32; ++h) {
        const size_t o = base + h * HDD;
        float q1 = q[o], q2 = q[o + 64];
        q[o]      = q1 * c - q2 * s;
        q[o + 64] = q2 * c + q1 * s;
        float k1 = k[o], k2 = k[o + 64];
        k[o]      = k1 * c - k2 * s;
        k[o + 64] = k2 * c + k1 * s;
    }
}

// ============================================================
// HMMA flash attention. Grid (qt=8, h=32, b=8), 128 threads.
// Q tile 64x128, KV tile 64. QK: fp16 hi/lo 3-term split (exact
// scores). PV: single fp16 (P in [0,1], V rounding ~2^-12).
// ============================================================
#define AQS 136                     // half-element row stride (272B; (17r+c)%8 conflict-free)
#define ATT_SMEM (5 * 64 * AQS * 2) // Qhi,Qlo,Khi,Klo,V = 87040 B

__global__ __launch_bounds__(128) void attn_mma(
    const float* __restrict__ qbuf, const float* __restrict__ knew,
    const float* __restrict__ vnew, const float* __restrict__ kcache,
    const float* __restrict__ vcache, const int* __restrict__ boff,
    float* __restrict__ obuf)
{
    extern __shared__ __half hsm[];
    __half* Qhi = hsm;
    __half* Qlo = Qhi + 64 * AQS;
    __half* Khi = Qlo + 64 * AQS;
    __half* Klo = Khi + 64 * AQS;
    __half* Vs  = Klo + 64 * AQS;

    const int qt = blockIdx.x, h = blockIdx.y, b = blockIdx.z;
    const int tid = threadIdx.x;
    const int lane = tid & 31, w = tid >> 5;
    const float scale = 0.08838834764831845f;

    // ---- load + split Q (scaled) ----
    {
        const int r = tid >> 1, cb = (tid & 1) * 64;
        const float* src = qbuf + (size_t)(b * QL + qt * 64 + r) * HID + h * HDD + cb;
        __half* dh = Qhi + r * AQS + cb;
        __half* dl = Qlo + r * AQS + cb;
#pragma unroll
        for (int i = 0; i < 16; i++) {
            float4 v = *(const float4*)(src + i * 4);
            v.x *= scale; v.y *= scale; v.z *= scale; v.w *= scale;
            __half hx = __float2half(v.x), hy = __float2half(v.y);
            __half hz = __float2half(v.z), hw = __float2half(v.w);
            dh[i*4+0] = hx; dh[i*4+1] = hy; dh[i*4+2] = hz; dh[i*4+3] = hw;
            dl[i*4+0] = __float2half(v.x - __half2float(hx));
            dl[i*4+1] = __float2half(v.y - __half2float(hy));
            dl[i*4+2] = __float2half(v.z - __half2float(hz));
            dl[i*4+3] = __float2half(v.w - __half2float(hw));
        }
    }

    float m0 = -1e30f, m1 = -1e30f, l0 = 0.f, l1 = 0.f;
    float o[16][4];
#pragma unroll
    for (int d = 0; d < 16; d++)
#pragma unroll
        for (int u = 0; u < 4; u++) o[d][u] = 0.f;

    const int r0 = lane >> 2;           // 0..7
    const int qrow0 = w * 16 + r0;      // local row in 64-tile
    const int qrow1 = qrow0 + 8;

    // fragment smem addresses (bytes)
    const uint32_t sb = smem_u32(hsm);
    const uint32_t aQh = sb + ((w * 16 + (lane & 15)) * AQS + (lane >> 4) * 8) * 2;
    const uint32_t aQl = aQh + 64 * AQS * 2;
    const uint32_t kbase = sb + 2 * 64 * AQS * 2;
    const uint32_t aKrow = ((lane & 7) + ((lane >> 4) << 3));
    const uint32_t aKcb  = ((lane >> 3) & 1) * 8;
    const uint32_t vbase = sb + 4 * 64 * AQS * 2;
    const uint32_t aVrow = ((lane & 7) + ((lane >> 3) & 1) * 8);
    const uint32_t aVcb  = (lane >> 4) * 8;

    const int ntiles = qt + 9;
    for (int kt = 0; kt < ntiles; kt++) {
        __syncthreads();   // previous tile's MMA reads done before overwrite
        // ---- gather K/V tile, convert to fp16 (K split hi/lo) ----
        {
            const int r = tid >> 1, cb = (tid & 1) * 64;
            const int p = kt * 64 + r;
            const float *ks, *vs;
            if (p < HIS) {
                int blk = boff[b * NBL + (p >> 6)];
                size_t base = (((size_t)blk * BSZ + (p & 63)) * NHD + h) * HDD + cb;
                ks = kcache + base; vs = vcache + base;
            } else {
                size_t base = (size_t)(b * QL + (p - HIS)) * HID + h * HDD + cb;
                ks = knew + base; vs = vnew + base;
            }
            __half* dkh = Khi + r * AQS + cb;
            __half* dkl = Klo + r * AQS + cb;
            __half* dv  = Vs  + r * AQS + cb;
#pragma unroll
            for (int i = 0; i < 16; i++) {
                float4 kv4 = *(const float4*)(ks + i * 4);
                __half hx = __float2half(kv4.x), hy = __float2half(kv4.y);
                __half hz = __float2half(kv4.z), hw = __float2half(kv4.w);
                dkh[i*4+0] = hx; dkh[i*4+1] = hy; dkh[i*4+2] = hz; dkh[i*4+3] = hw;
                dkl[i*4+0] = __float2half(kv4.x - __half2float(hx));
                dkl[i*4+1] = __float2half(kv4.y - __half2float(hy));
                dkl[i*4+2] = __float2half(kv4.z - __half2float(hz));
                dkl[i*4+3] = __float2half(kv4.w - __half2float(hw));
                float4 v4 = *(const float4*)(vs + i * 4);
                *(__half2*)(dv + i*4)     = __floats2half2_rn(v4.x, v4.y);
                *(__half2*)(dv + i*4 + 2) = __floats2half2_rn(v4.z, v4.w);
            }
        }
        __syncthreads();

        // ---- S = Q K^T (3-term fp16 split) ----
        float S[8][4];
#pragma unroll
        for (int f = 0; f < 8; f++)
#pragma unroll
            for (int u = 0; u < 4; u++) S[f][u] = 0.f;

#pragma unroll
        for (int kc = 0; kc < 8; kc++) {
            uint32_t qh[4], ql[4];
            ldm4(qh, aQh + kc * 32);
            ldm4(ql, aQl + kc * 32);
#pragma unroll
            for (int jp = 0; jp < 4; jp++) {
                uint32_t kh[4], kl[4];
                const uint32_t ka = kbase + ((jp * 16 + aKrow) * AQS + aKcb + kc * 16) * 2;
                ldm4(kh, ka);
                ldm4(kl, ka + 64 * AQS * 2);
                mmah(S[2*jp],   qh, &kh[0]);
                mmah(S[2*jp],   qh, &kl[0]);
                mmah(S[2*jp],   ql, &kh[0]);
                mmah(S[2*jp+1], qh, &kh[2]);
                mmah(S[2*jp+1], qh, &kl[2]);
                mmah(S[2*jp+1], ql, &kh[2]);
            }
        }

        // ---- causal mask (diagonal tile only) ----
        if (kt == qt + 8) {
#pragma unroll
            for (int f = 0; f < 8; f++) {
                int c0 = f * 8 + (lane & 3) * 2;
                if (c0     > qrow0) S[f][0] = -1e30f;
                if (c0 + 1 > qrow0) S[f][1] = -1e30f;
                if (c0     > qrow1) S[f][2] = -1e30f;
                if (c0 + 1 > qrow1) S[f][3] = -1e30f;
            }
        }

        // ---- online softmax ----
        float tm0 = -1e30f, tm1 = -1e30f;
#pragma unroll
        for (int f = 0; f < 8; f++) {
            tm0 = fmaxf(tm0, fmaxf(S[f][0], S[f][1]));
            tm1 = fmaxf(tm1, fmaxf(S[f][2], S[f][3]));
        }
        tm0 = fmaxf(tm0, __shfl_xor_sync(0xffffffffu, tm0, 1));
        tm0 = fmaxf(tm0, __shfl_xor_sync(0xffffffffu, tm0, 2));
        tm1 = fmaxf(tm1, __shfl_xor_sync(0xffffffffu, tm1, 1));
        tm1 = fmaxf(tm1, __shfl_xor_sync(0xffffffffu, tm1, 2));
        const float mn0 = fmaxf(m0, tm0), mn1 = fmaxf(m1, tm1);
        const float al0 = fexp(m0 - mn0), al1 = fexp(m1 - mn1);

        float s0 = 0.f, s1 = 0.f;
#pragma unroll
        for (int f = 0; f < 8; f++) {
            S[f][0] = fexp(S[f][0] - mn0);
            S[f][1] = fexp(S[f][1] - mn0);
            S[f][2] = fexp(S[f][2] - mn1);
            S[f][3] = fexp(S[f][3] - mn1);
            s0 += S[f][0] + S[f][1];
            s1 += S[f][2] + S[f][3];
        }
        s0 += __shfl_xor_sync(0xffffffffu, s0, 1);
        s0 += __shfl_xor_sync(0xffffffffu, s0, 2);
        s1 += __shfl_xor_sync(0xffffffffu, s1, 1);
        s1 += __shfl_xor_sync(0xffffffffu, s1, 2);
        l0 = l0 * al0 + s0;
        l1 = l1 * al1 + s1;
        m0 = mn0; m1 = mn1;

        // rescale O
#pragma unroll
        for (int d = 0; d < 16; d++) {
            o[d][0] *= al0; o[d][1] *= al0;
            o[d][2] *= al1; o[d][3] *= al1;
        }

        // ---- P fragments (c-layout == a-layout) ----
        uint32_t pa[4][4];
#pragma unroll
        for (int kk = 0; kk < 4; kk++) {
            pa[kk][0] = packh2(S[2*kk][0],   S[2*kk][1]);
            pa[kk][1] = packh2(S[2*kk][2],   S[2*kk][3]);
            pa[kk][2] = packh2(S[2*kk+1][0], S[2*kk+1][1]);
            pa[kk][3] = packh2(S[2*kk+1][2], S[2*kk+1][3]);
        }

        // ---- O += P V (single fp16) ----
#pragma unroll
        for (int kk = 0; kk < 4; kk++) {
#pragma unroll
            for (int dg = 0; dg < 8; dg++) {
                uint32_t bv[4];
                ldm4t(bv, vbase + ((kk * 16 + aVrow) * AQS + dg * 16 + aVcb) * 2);
                mmah(o[dg*2],   pa[kk], &bv[0]);
                mmah(o[dg*2+1], pa[kk], &bv[2]);
            }
        }
    }

    // ---- normalize + write ----
    const float inv0 = 1.f / l0, inv1 = 1.f / l1;
    const int gr0 = b * QL + qt * 64 + qrow0;
    const int gr1 = gr0 + 8;
    const int col = h * HDD + (lane & 3) * 2;
#pragma unroll
    for (int d = 0; d < 16; d++) {
        *(float2*)(obuf + (size_t)gr0 * HID + col + d * 8) = make_float2(o[d][0] * inv0, o[d][1] * inv0);
        *(float2*)(obuf + (size_t)gr1 * HID + col + d * 8) = make_float2(o[d][2] * inv1, o[d][3] * inv1);
    }
}

// ============================================================
// launch
// ============================================================
extern "C" void kernel_launch(void* const* d_in, const int* in_sizes, int n_in,
                              void* d_out, int out_size)
{
    const float* hidden = (const float*)d_in[0];
    const float* Wq     = (const float*)d_in[1];
    const float* Wk     = (const float*)d_in[2];
    const float* Wv     = (const float*)d_in[3];
    const float* Wo     = (const float*)d_in[4];
    const float* kcache = (const float*)d_in[5];
    const float* vcache = (const float*)d_in[6];
    const int*   boff   = (const int*)d_in[7];
    const int*   pos    = (const int*)d_in[8];
    float* out = (float*)d_out;

    float *gq, *gk, *gv, *ga;
    __half *ah, *wt;
    cudaGetSymbolAddress((void**)&gq, g_q);
    cudaGetSymbolAddress((void**)&gk, g_k);
    cudaGetSymbolAddress((void**)&gv, g_v);
    cudaGetSymbolAddress((void**)&ga, g_att);
    cudaGetSymbolAddress((void**)&ah, g_Ah);
    cudaGetSymbolAddress((void**)&wt, g_Wt);

    cudaFuncSetAttribute(gemm_fp16, cudaFuncAttributeMaxDynamicSharedMemorySize, GEMM_SMEM);
    cudaFuncSetAttribute(attn_mma, cudaFuncAttributeMaxDynamicSharedMemorySize, ATT_SMEM);

    const int ncvt = TOK * HID / 4 / 256;
    dim3 tgrid(HID / 32, HID / 32);
    dim3 ggrid(HID / 128, TOK / 128);

    cvt_half<<<ncvt, 256>>>((const float4*)hidden, ah);
    transpose_half<<<tgrid, 256>>>(Wq, wt + 0 * (size_t)HID * HID);
    transpose_half<<<tgrid, 256>>>(Wk, wt + 1 * (size_t)HID * HID);
    transpose_half<<<tgrid, 256>>>(Wv, wt + 2 * (size_t)HID * HID);
    transpose_half<<<tgrid, 256>>>(Wo, wt + 3 * (size_t)HID * HID);

    gemm_fp16<<<ggrid, 256, GEMM_SMEM>>>(ah, wt + 0 * (size_t)HID * HID, gq);
    gemm_fp16<<<ggrid, 256, GEMM_SMEM>>>(ah, wt + 1 * (size_t)HID * HID, gk);
    gemm_fp16<<<ggrid, 256, GEMM_SMEM>>>(ah, wt + 2 * (size_t)HID * HID, gv);

    rope_kernel2<<<TOK * 64 / 256, 256>>>(gq, gk, pos);

    dim3 ag(QL / 64, NHD, NB);
    attn_mma<<<ag, 128, ATT_SMEM>>>(gq, gk, gv, kcache, vcache, boff, ga);

    cvt_half<<<ncvt, 256>>>((const float4*)ga, ah);
    gemm_fp16<<<ggrid, 256, GEMM_SMEM>>>(ah, wt + 3 * (size_t)HID * HID, out);
}

// round 6
// speedup vs baseline: 8.2579x; 1.3018x over previous
#include <cuda_runtime.h>
#include <cuda_fp16.h>
#include <math.h>
#include <stdint.h>

// ---- problem constants ----
#define TOK  4096
#define HID  4096
#define NHD  32
#define HDD  128
#define NB   8
#define QL   512
#define HIS  512
#define BSZ  64
#define NBL  16

// ---- scratch ----
__device__ float g_q[TOK * HID];
__device__ float g_k[TOK * HID];
__device__ float g_v[TOK * HID];
__device__ __half g_Ah[TOK * HID];          // GEMM A operand (hidden, later attn out)
__device__ __half g_Wt[4][HID * HID];       // transposed weights [N,K] fp16
__device__ __half g_Khi[NB * NHD * 1024 * HDD];
__device__ __half g_Klo[NB * NHD * 1024 * HDD];
__device__ __half g_Vh [NB * NHD * 1024 * HDD];

// ============================================================
// helpers
// ============================================================
__device__ __forceinline__ uint32_t smem_u32(const void* p) {
    uint32_t a;
    asm("{ .reg .u64 t; cvta.to.shared.u64 t, %1; cvt.u32.u64 %0, t; }" : "=r"(a) : "l"(p));
    return a;
}
__device__ __forceinline__ void cp16(uint32_t dst, const void* src) {
    asm volatile("cp.async.cg.shared.global [%0], [%1], 16;" :: "r"(dst), "l"(src));
}
__device__ __forceinline__ void cp_commit() {
    asm volatile("cp.async.commit_group;" ::: "memory");
}
template <int N> __device__ __forceinline__ void cp_wait() {
    asm volatile("cp.async.wait_group %0;" :: "n"(N) : "memory");
}
__device__ __forceinline__ void ldm4(uint32_t* r, uint32_t addr) {
    asm volatile("ldmatrix.sync.aligned.m8n8.x4.shared.b16 {%0,%1,%2,%3}, [%4];"
                 : "=r"(r[0]), "=r"(r[1]), "=r"(r[2]), "=r"(r[3]) : "r"(addr));
}
__device__ __forceinline__ void ldm4t(uint32_t* r, uint32_t addr) {
    asm volatile("ldmatrix.sync.aligned.m8n8.x4.trans.shared.b16 {%0,%1,%2,%3}, [%4];"
                 : "=r"(r[0]), "=r"(r[1]), "=r"(r[2]), "=r"(r[3]) : "r"(addr));
}
__device__ __forceinline__ void mmah(float* d, const uint32_t* a, const uint32_t* b) {
    asm volatile(
        "mma.sync.aligned.m16n8k16.row.col.f32.f16.f16.f32 "
        "{%0,%1,%2,%3}, {%4,%5,%6,%7}, {%8,%9}, {%0,%1,%2,%3};"
        : "+f"(d[0]), "+f"(d[1]), "+f"(d[2]), "+f"(d[3])
        : "r"(a[0]), "r"(a[1]), "r"(a[2]), "r"(a[3]), "r"(b[0]), "r"(b[1]));
}
__device__ __forceinline__ uint32_t packh2(float x, float y) {
    __half2 h = __floats2half2_rn(x, y);
    return *reinterpret_cast<uint32_t*>(&h);
}
__device__ __forceinline__ float fexp(float x) {
    float t = fmaxf(x * 1.4426950408889634f, -80.0f);
    int   i = __float2int_rn(t);
    float f = t - (float)i;
    float p = 0.0013333558f;
    p = fmaf(p, f, 0.0096181291f);
    p = fmaf(p, f, 0.0555041087f);
    p = fmaf(p, f, 0.2402265069f);
    p = fmaf(p, f, 0.6931471806f);
    p = fmaf(p, f, 1.0f);
    return p * __int_as_float((i + 127) << 23);
}

// ============================================================
// fp32 -> fp16 convert
// ============================================================
__global__ __launch_bounds__(256) void cvt_half(const float4* __restrict__ src,
                                                __half* __restrict__ dst)
{
    int i = blockIdx.x * 256 + threadIdx.x;
    float4 v = src[i];
    __half2* d = (__half2*)dst;
    d[i * 2]     = __floats2half2_rn(v.x, v.y);
    d[i * 2 + 1] = __floats2half2_rn(v.z, v.w);
}

// ============================================================
// Transpose W[K,N] fp32 -> Wt[N,K] fp16
// ============================================================
__global__ __launch_bounds__(256) void transpose_half(const float* __restrict__ W,
                                                      __half* __restrict__ dst)
{
    __shared__ float tile[32][33];
    const int bx = blockIdx.x, by = blockIdx.y;
    const int tx = threadIdx.x & 31, ty = threadIdx.x >> 5;
#pragma unroll
    for (int j = 0; j < 4; j++)
        tile[ty + j * 8][tx] = W[(size_t)(by * 32 + ty + j * 8) * HID + bx * 32 + tx];
    __syncthreads();
#pragma unroll
    for (int j = 0; j < 4; j++) {
        float v = tile[tx][ty + j * 8];
        dst[(size_t)(bx * 32 + ty + j * 8) * HID + by * 32 + tx] = __float2half(v);
    }
}

// ============================================================
// fp16 HMMA GEMM: C[4096,4096] = A @ Bt^T  (fp32 accumulate)
// CTA 128x128, BK=32, 3-stage cp.async, 4 warps, warp tile 64x64.
// ============================================================
#define ROWB   80
#define TILEB  (128 * ROWB)
#define STAGEB (2 * TILEB)
#define GEMM_SMEM (3 * STAGEB)   // 61440

__global__ __launch_bounds__(128, 2) void gemm_fp16(const __half* __restrict__ A,
                                                    const __half* __restrict__ B,
                                                    float* __restrict__ C)
{
    extern __shared__ char smem[];
    const uint32_t sbase = smem_u32(smem);
    const int tid = threadIdx.x;
    const int lane = tid & 31, wid = tid >> 5;
    const int wm = wid & 1, wn = wid >> 1;     // 2x2 warp grid, warp tile 64x64
    const int row0 = blockIdx.y * 128, col0 = blockIdx.x * 128;

    const __half* tsrc[2] = { A + (size_t)row0 * HID, B + (size_t)col0 * HID };

    auto fill = [&](int stage, int kblk) {
        const uint32_t sb = sbase + stage * STAGEB;
        const int koff = kblk * 32;
#pragma unroll
        for (int i = 0; i < 8; i++) {
            int id = tid + i * 128;
            int t = id >> 9;
            int r = (id >> 2) & 127;
            int c = id & 3;
            cp16(sb + t * TILEB + r * ROWB + c * 16,
                 tsrc[t] + (size_t)r * HID + koff + c * 8);
        }
        cp_commit();
    };

    float acc[4][8][4];
#pragma unroll
    for (int i = 0; i < 4; i++)
#pragma unroll
        for (int j = 0; j < 8; j++)
#pragma unroll
            for (int u = 0; u < 4; u++) acc[i][j][u] = 0.f;

    fill(0, 0); fill(1, 1); fill(2, 2);

    const int a_row = (lane & 15);
    const int a_cb  = (lane >> 4) * 16;
    const int b_row = (lane & 7) + ((lane >> 4) << 3);
    const int b_cb  = ((lane >> 3) & 1) * 16;

    const int NKB = HID / 32;
    for (int c = 0; c < NKB; ++c) {
        const int s = c % 3;
        cp_wait<2>();
        __syncthreads();
        const uint32_t sb = sbase + s * STAGEB;
        const uint32_t aA = sb + (wm * 64 + a_row) * ROWB + a_cb;
        const uint32_t aB = sb + TILEB + (wn * 64 + b_row) * ROWB + b_cb;

#pragma unroll
        for (int ks = 0; ks < 2; ++ks) {
            const int kb = ks * 32;
            uint32_t a[4][4], b[4][4];
#pragma unroll
            for (int i = 0; i < 4; i++) ldm4(a[i], aA + i * (16 * ROWB) + kb);
#pragma unroll
            for (int j = 0; j < 4; j++) ldm4(b[j], aB + j * (16 * ROWB) + kb);
#pragma unroll
            for (int i = 0; i < 4; i++)
#pragma unroll
                for (int j = 0; j < 8; j++)
                    mmah(acc[i][j], a[i], &b[j >> 1][(j & 1) * 2]);
        }
        __syncthreads();
        if (c + 3 < NKB) fill(s, c + 3);
        else cp_commit();
    }

    const int erow = row0 + wm * 64 + (lane >> 2);
    const int ecol = col0 + wn * 64 + (lane & 3) * 2;
#pragma unroll
    for (int i = 0; i < 4; i++)
#pragma unroll
        for (int j = 0; j < 8; j++) {
            float* p0 = C + (size_t)(erow + i * 16) * HID + ecol + j * 8;
            float* p1 = C + (size_t)(erow + i * 16 + 8) * HID + ecol + j * 8;
            *(float2*)p0 = make_float2(acc[i][j][0], acc[i][j][1]);
            *(float2*)p1 = make_float2(acc[i][j][2], acc[i][j][3]);
        }
}

// ============================================================
// RoPE
// ============================================================
__global__ __launch_bounds__(256) void rope_kernel2(float* __restrict__ q,
                                                    float* __restrict__ k,
                                                    const int* __restrict__ pos)
{
    const int idx = blockIdx.x * 256 + threadIdx.x;
    const int j = idx & 63, t = idx >> 6;
    const double inv_freq = exp2(-(double)j * (13.287712379549449 / 64.0));
    const double ang = (double)pos[t] * inv_freq;
    const float a = (float)remainder(ang, 6.283185307179586476925286766559);
    const float c = cosf(a), s = sinf(a);
    const size_t base = (size_t)t * HID + j;
#pragma unroll 4
    for (int h = 0; h < 32; ++h) {
        const size_t o = base + h * HDD;
        float q1 = q[o], q2 = q[o + 64];
        q[o]      = q1 * c - q2 * s;
        q[o + 64] = q2 * c + q1 * s;
        float k1 = k[o], k2 = k[o + 64];
        k[o]      = k1 * c - k2 * s;
        k[o + 64] = k2 * c + k1 * s;
    }
}

// ============================================================
// KV prep: gather paged cache (or new tokens) -> contiguous
// [b][h][kv=1024][128] fp16 buffers. K split hi/lo, V single.
// One warp per (b,h,p) row.
// ============================================================
__global__ __launch_bounds__(256) void prep_kv(
    const float* __restrict__ kcache, const float* __restrict__ vcache,
    const float* __restrict__ knew,  const float* __restrict__ vnew,
    const int* __restrict__ boff,
    __half* __restrict__ Khi, __half* __restrict__ Klo, __half* __restrict__ Vh)
{
    const int rowid = blockIdx.x * 8 + (threadIdx.x >> 5);
    const int lane = threadIdx.x & 31;
    const int p = rowid & 1023;
    const int h = (rowid >> 10) & 31;
    const int b = rowid >> 15;

    const float *ks, *vs;
    if (p < HIS) {
        int blk = boff[b * NBL + (p >> 6)];
        size_t base = (((size_t)blk * BSZ + (p & 63)) * NHD + h) * HDD;
        ks = kcache + base; vs = vcache + base;
    } else {
        size_t base = ((size_t)(b * QL + p - HIS)) * HID + h * HDD;
        ks = knew + base; vs = vnew + base;
    }
    float4 kv = *(const float4*)(ks + lane * 4);
    float4 vv = *(const float4*)(vs + lane * 4);

    __half khx = __float2half(kv.x), khy = __float2half(kv.y);
    __half khz = __float2half(kv.z), khw = __float2half(kv.w);
    __half klx = __float2half(kv.x - __half2float(khx));
    __half kly = __float2half(kv.y - __half2float(khy));
    __half klz = __float2half(kv.z - __half2float(khz));
    __half klw = __float2half(kv.w - __half2float(khw));

    const size_t o = (size_t)rowid * HDD + lane * 4;
    *(__half2*)(Khi + o)     = __half2(khx, khy);
    *(__half2*)(Khi + o + 2) = __half2(khz, khw);
    *(__half2*)(Klo + o)     = __half2(klx, kly);
    *(__half2*)(Klo + o + 2) = __half2(klz, klw);
    *(__half2*)(Vh + o)      = __floats2half2_rn(vv.x, vv.y);
    *(__half2*)(Vh + o + 2)  = __floats2half2_rn(vv.z, vv.w);
}

// ============================================================
// HMMA flash attention v2. Grid (qt=4, h=32, b=8), 256 threads.
// Q tile 128x128 (8 warps x 16 rows), KV tile 64, 2-stage
// cp.async pipeline over prepped fp16 KV. Output fp16.
// ============================================================
#define AS 136
#define QLO_OFF (128 * AS)            // halfs
#define KV_BASE (2 * 128 * AS)        // halfs
#define KV_STG  (3 * 64 * AS)         // halfs per stage (Khi, Klo, V)
#define ATT_SMEM ((KV_BASE + 2 * KV_STG) * 2)   // 174080 bytes

__global__ __launch_bounds__(256, 1) void attn_mma(
    const float* __restrict__ qbuf,
    const __half* __restrict__ Khi, const __half* __restrict__ Klo,
    const __half* __restrict__ Vh, __half* __restrict__ obuf)
{
    extern __shared__ __half hsm[];
    const int qt = blockIdx.x, h = blockIdx.y, b = blockIdx.z;
    const int tid = threadIdx.x;
    const int lane = tid & 31, w = tid >> 5;
    const float scale = 0.08838834764831845f;

    // ---- load + split + scale Q tile (128 x 128) ----
    {
        const int r = tid >> 1, cb = (tid & 1) * 64;
        const float* src = qbuf + (size_t)(b * QL + qt * 128 + r) * HID + h * HDD + cb;
        __half* dh = hsm + r * AS + cb;
        __half* dl = dh + QLO_OFF;
#pragma unroll
        for (int i = 0; i < 16; i++) {
            float4 v = *(const float4*)(src + i * 4);
            v.x *= scale; v.y *= scale; v.z *= scale; v.w *= scale;
            __half hx = __float2half(v.x), hy = __float2half(v.y);
            __half hz = __float2half(v.z), hw = __float2half(v.w);
            dh[i*4+0] = hx; dh[i*4+1] = hy; dh[i*4+2] = hz; dh[i*4+3] = hw;
            dl[i*4+0] = __float2half(v.x - __half2float(hx));
            dl[i*4+1] = __float2half(v.y - __half2float(hy));
            dl[i*4+2] = __float2half(v.z - __half2float(hz));
            dl[i*4+3] = __float2half(v.w - __half2float(hw));
        }
    }

    const size_t kvoff = ((size_t)(b * NHD + h)) * 1024 * HDD;
    const __half* kp[3] = { Khi + kvoff, Klo + kvoff, Vh + kvoff };
    const uint32_t sb = smem_u32(hsm);

    auto fill = [&](int stage, int kt) {
#pragma unroll
        for (int i = 0; i < 12; i++) {
            int id = tid + i * 256;
            int buf = id >> 10;
            int r = (id >> 4) & 63;
            int c = id & 15;
            uint32_t dst = sb + (uint32_t)(KV_BASE + stage * KV_STG + buf * (64 * AS) + r * AS + c * 8) * 2;
            cp16(dst, kp[buf] + (size_t)(kt * 64 + r) * HDD + c * 8);
        }
        cp_commit();
    };

    float m0 = -1e30f, m1 = -1e30f, l0 = 0.f, l1 = 0.f;
    float o[16][4];
#pragma unroll
    for (int d = 0; d < 16; d++)
#pragma unroll
        for (int u = 0; u < 4; u++) o[d][u] = 0.f;

    const int r0 = lane >> 2;
    const int qp0 = HIS + qt * 128 + w * 16 + r0;     // global q position
    const int qp1 = qp0 + 8;

    const uint32_t aQh = sb + ((w * 16 + (lane & 15)) * AS + (lane >> 4) * 8) * 2;
    const uint32_t aQl = aQh + QLO_OFF * 2;
    const uint32_t aKrow = (lane & 7) + ((lane >> 4) << 3);
    const uint32_t aKcb  = ((lane >> 3) & 1) * 8;     // halfs
    const uint32_t aVrow = (lane & 7) + ((lane >> 3) & 1) * 8;
    const uint32_t aVcb  = (lane >> 4) * 8;           // halfs

    const int ntiles = 10 + 2 * qt;
    fill(0, 0); fill(1, 1);

    for (int kt = 0; kt < ntiles; kt++) {
        const int s = kt & 1;
        cp_wait<1>();
        __syncthreads();
        const uint32_t kbs = sb + (uint32_t)(KV_BASE + s * KV_STG) * 2;   // Khi
        const uint32_t vbs = kbs + (uint32_t)(2 * 64 * AS) * 2;           // V

        // ---- S = Q K^T (3-term fp16 split) ----
        float S[8][4];
#pragma unroll
        for (int f = 0; f < 8; f++)
#pragma unroll
            for (int u = 0; u < 4; u++) S[f][u] = 0.f;

#pragma unroll
        for (int kc = 0; kc < 8; kc++) {
            uint32_t qh[4], ql[4];
            ldm4(qh, aQh + kc * 32);
            ldm4(ql, aQl + kc * 32);
#pragma unroll
            for (int jp = 0; jp < 4; jp++) {
                uint32_t kh[4], kl[4];
                const uint32_t ka = kbs + ((jp * 16 + aKrow) * AS + aKcb + kc * 16) * 2;
                ldm4(kh, ka);
                ldm4(kl, ka + (uint32_t)(64 * AS) * 2);
                mmah(S[2*jp],   qh, &kh[0]);
                mmah(S[2*jp],   qh, &kl[0]);
                mmah(S[2*jp],   ql, &kh[0]);
                mmah(S[2*jp+1], qh, &kh[2]);
                mmah(S[2*jp+1], qh, &kl[2]);
                mmah(S[2*jp+1], ql, &kh[2]);
            }
        }

        // ---- causal mask (diagonal band: last two tiles) ----
        if (kt >= ntiles - 2) {
#pragma unroll
            for (int f = 0; f < 8; f++) {
                int c0 = kt * 64 + f * 8 + (lane & 3) * 2;
                if (c0     > qp0) S[f][0] = -1e30f;
                if (c0 + 1 > qp0) S[f][1] = -1e30f;
                if (c0     > qp1) S[f][2] = -1e30f;
                if (c0 + 1 > qp1) S[f][3] = -1e30f;
            }
        }

        // ---- online softmax ----
        float tm0 = -1e30f, tm1 = -1e30f;
#pragma unroll
        for (int f = 0; f < 8; f++) {
            tm0 = fmaxf(tm0, fmaxf(S[f][0], S[f][1]));
            tm1 = fmaxf(tm1, fmaxf(S[f][2], S[f][3]));
        }
        tm0 = fmaxf(tm0, __shfl_xor_sync(0xffffffffu, tm0, 1));
        tm0 = fmaxf(tm0, __shfl_xor_sync(0xffffffffu, tm0, 2));
        tm1 = fmaxf(tm1, __shfl_xor_sync(0xffffffffu, tm1, 1));
        tm1 = fmaxf(tm1, __shfl_xor_sync(0xffffffffu, tm1, 2));
        const float mn0 = fmaxf(m0, tm0), mn1 = fmaxf(m1, tm1);
        const float al0 = fexp(m0 - mn0), al1 = fexp(m1 - mn1);

        float s0 = 0.f, s1 = 0.f;
#pragma unroll
        for (int f = 0; f < 8; f++) {
            S[f][0] = fexp(S[f][0] - mn0);
            S[f][1] = fexp(S[f][1] - mn0);
            S[f][2] = fexp(S[f][2] - mn1);
            S[f][3] = fexp(S[f][3] - mn1);
            s0 += S[f][0] + S[f][1];
            s1 += S[f][2] + S[f][3];
        }
        s0 += __shfl_xor_sync(0xffffffffu, s0, 1);
        s0 += __shfl_xor_sync(0xffffffffu, s0, 2);
        s1 += __shfl_xor_sync(0xffffffffu, s1, 1);
        s1 += __shfl_xor_sync(0xffffffffu, s1, 2);
        l0 = l0 * al0 + s0;
        l1 = l1 * al1 + s1;
        m0 = mn0; m1 = mn1;

#pragma unroll
        for (int d = 0; d < 16; d++) {
            o[d][0] *= al0; o[d][1] *= al0;
            o[d][2] *= al1; o[d][3] *= al1;
        }

        uint32_t pa[4][4];
#pragma unroll
        for (int kk = 0; kk < 4; kk++) {
            pa[kk][0] = packh2(S[2*kk][0],   S[2*kk][1]);
            pa[kk][1] = packh2(S[2*kk][2],   S[2*kk][3]);
            pa[kk][2] = packh2(S[2*kk+1][0], S[2*kk+1][1]);
            pa[kk][3] = packh2(S[2*kk+1][2], S[2*kk+1][3]);
        }

        // ---- O += P V ----
#pragma unroll
        for (int kk = 0; kk < 4; kk++) {
#pragma unroll
            for (int dg = 0; dg < 8; dg++) {
                uint32_t bv[4];
                ldm4t(bv, vbs + ((kk * 16 + aVrow) * AS + dg * 16 + aVcb) * 2);
                mmah(o[dg*2],   pa[kk], &bv[0]);
                mmah(o[dg*2+1], pa[kk], &bv[2]);
            }
        }

        __syncthreads();
        if (kt + 2 < ntiles) fill(s, kt + 2);
        else cp_commit();
    }

    // ---- normalize + write fp16 ----
    const float inv0 = 1.f / l0, inv1 = 1.f / l1;
    const int gr0 = b * QL + qt * 128 + w * 16 + r0;
    const int gr1 = gr0 + 8;
    const int col = h * HDD + (lane & 3) * 2;
#pragma unroll
    for (int d = 0; d < 16; d++) {
        *(__half2*)(obuf + (size_t)gr0 * HID + col + d * 8) = __floats2half2_rn(o[d][0] * inv0, o[d][1] * inv0);
        *(__half2*)(obuf + (size_t)gr1 * HID + col + d * 8) = __floats2half2_rn(o[d][2] * inv1, o[d][3] * inv1);
    }
}

// ============================================================
// launch
// ============================================================
extern "C" void kernel_launch(void* const* d_in, const int* in_sizes, int n_in,
                              void* d_out, int out_size)
{
    const float* hidden = (const float*)d_in[0];
    const float* Wq     = (const float*)d_in[1];
    const float* Wk     = (const float*)d_in[2];
    const float* Wv     = (const float*)d_in[3];
    const float* Wo     = (const float*)d_in[4];
    const float* kcache = (const float*)d_in[5];
    const float* vcache = (const float*)d_in[6];
    const int*   boff   = (const int*)d_in[7];
    const int*   pos    = (const int*)d_in[8];
    float* out = (float*)d_out;

    float *gq, *gk, *gv;
    __half *ah, *wt, *khi, *klo, *vh;
    cudaGetSymbolAddress((void**)&gq, g_q);
    cudaGetSymbolAddress((void**)&gk, g_k);
    cudaGetSymbolAddress((void**)&gv, g_v);
    cudaGetSymbolAddress((void**)&ah, g_Ah);
    cudaGetSymbolAddress((void**)&wt, g_Wt);
    cudaGetSymbolAddress((void**)&khi, g_Khi);
    cudaGetSymbolAddress((void**)&klo, g_Klo);
    cudaGetSymbolAddress((void**)&vh, g_Vh);

    cudaFuncSetAttribute(gemm_fp16, cudaFuncAttributeMaxDynamicSharedMemorySize, GEMM_SMEM);
    cudaFuncSetAttribute(attn_mma, cudaFuncAttributeMaxDynamicSharedMemorySize, ATT_SMEM);

    const int ncvt = TOK * HID / 4 / 256;
    dim3 tgrid(HID / 32, HID / 32);
    dim3 ggrid(HID / 128, TOK / 128);

    cvt_half<<<ncvt, 256>>>((const float4*)hidden, ah);
    transpose_half<<<tgrid, 256>>>(Wq, wt + 0 * (size_t)HID * HID);
    transpose_half<<<tgrid, 256>>>(Wk, wt + 1 * (size_t)HID * HID);
    transpose_half<<<tgrid, 256>>>(Wv, wt + 2 * (size_t)HID * HID);
    transpose_half<<<tgrid, 256>>>(Wo, wt + 3 * (size_t)HID * HID);

    gemm_fp16<<<ggrid, 128, GEMM_SMEM>>>(ah, wt + 0 * (size_t)HID * HID, gq);
    gemm_fp16<<<ggrid, 128, GEMM_SMEM>>>(ah, wt + 1 * (size_t)HID * HID, gk);
    gemm_fp16<<<ggrid, 128, GEMM_SMEM>>>(ah, wt + 2 * (size_t)HID * HID, gv);

    rope_kernel2<<<TOK * 64 / 256, 256>>>(gq, gk, pos);

    prep_kv<<<NB * NHD * 1024 / 8, 256>>>(kcache, vcache, gk, gv, boff, khi, klo, vh);

    dim3 ag(QL / 128, NHD, NB);
    attn_mma<<<ag, 256, ATT_SMEM>>>(gq, khi, klo, vh, ah);

    gemm_fp16<<<ggrid, 128, GEMM_SMEM>>>(ah, wt + 3 * (size_t)HID * HID, out);
}

// round 7
// speedup vs baseline: 8.6824x; 1.0514x over previous
#include <cuda_runtime.h>
#include <cuda_fp16.h>
#include <math.h>
#include <stdint.h>

// ---- problem constants ----
#define TOK  4096
#define HID  4096
#define NHD  32
#define HDD  128
#define NB   8
#define QL   512
#define HIS  512
#define BSZ  64
#define NBL  16

// ---- scratch ----
__device__ float g_q[TOK * HID];
__device__ float g_k[TOK * HID];
__device__ float g_v[TOK * HID];
__device__ __half g_Ah[TOK * HID];          // GEMM A operand (hidden, later attn out)
__device__ __half g_Wt[4][HID * HID];       // transposed weights [N,K] fp16
__device__ __half g_Khi[NB * NHD * 1024 * HDD];
__device__ __half g_Klo[NB * NHD * 1024 * HDD];
__device__ __half g_Vh [NB * NHD * 1024 * HDD];

// ============================================================
// helpers
// ============================================================
__device__ __forceinline__ uint32_t smem_u32(const void* p) {
    uint32_t a;
    asm("{ .reg .u64 t; cvta.to.shared.u64 t, %1; cvt.u32.u64 %0, t; }" : "=r"(a) : "l"(p));
    return a;
}
__device__ __forceinline__ void cp16(uint32_t dst, const void* src) {
    asm volatile("cp.async.cg.shared.global [%0], [%1], 16;" :: "r"(dst), "l"(src));
}
__device__ __forceinline__ void cp_commit() {
    asm volatile("cp.async.commit_group;" ::: "memory");
}
template <int N> __device__ __forceinline__ void cp_wait() {
    asm volatile("cp.async.wait_group %0;" :: "n"(N) : "memory");
}
__device__ __forceinline__ void ldm4(uint32_t* r, uint32_t addr) {
    asm volatile("ldmatrix.sync.aligned.m8n8.x4.shared.b16 {%0,%1,%2,%3}, [%4];"
                 : "=r"(r[0]), "=r"(r[1]), "=r"(r[2]), "=r"(r[3]) : "r"(addr));
}
__device__ __forceinline__ void ldm4t(uint32_t* r, uint32_t addr) {
    asm volatile("ldmatrix.sync.aligned.m8n8.x4.trans.shared.b16 {%0,%1,%2,%3}, [%4];"
                 : "=r"(r[0]), "=r"(r[1]), "=r"(r[2]), "=r"(r[3]) : "r"(addr));
}
__device__ __forceinline__ void mmah(float* d, const uint32_t* a, const uint32_t* b) {
    asm volatile(
        "mma.sync.aligned.m16n8k16.row.col.f32.f16.f16.f32 "
        "{%0,%1,%2,%3}, {%4,%5,%6,%7}, {%8,%9}, {%0,%1,%2,%3};"
        : "+f"(d[0]), "+f"(d[1]), "+f"(d[2]), "+f"(d[3])
        : "r"(a[0]), "r"(a[1]), "r"(a[2]), "r"(a[3]), "r"(b[0]), "r"(b[1]));
}
__device__ __forceinline__ uint32_t packh2(float x, float y) {
    __half2 h = __floats2half2_rn(x, y);
    return *reinterpret_cast<uint32_t*>(&h);
}
__device__ __forceinline__ float fexp(float x) {
    float t = fmaxf(x * 1.4426950408889634f, -80.0f);
    int   i = __float2int_rn(t);
    float f = t - (float)i;
    float p = 0.0013333558f;
    p = fmaf(p, f, 0.0096181291f);
    p = fmaf(p, f, 0.0555041087f);
    p = fmaf(p, f, 0.2402265069f);
    p = fmaf(p, f, 0.6931471806f);
    p = fmaf(p, f, 1.0f);
    return p * __int_as_float((i + 127) << 23);
}

// ============================================================
// fp32 -> fp16 convert
// ============================================================
__global__ __launch_bounds__(256) void cvt_half(const float4* __restrict__ src,
                                                __half* __restrict__ dst)
{
    int i = blockIdx.x * 256 + threadIdx.x;
    float4 v = src[i];
    __half2* d = (__half2*)dst;
    d[i * 2]     = __floats2half2_rn(v.x, v.y);
    d[i * 2 + 1] = __floats2half2_rn(v.z, v.w);
}

// ============================================================
// Transpose 4 weights W[K,N] fp32 -> Wt[N,K] fp16 (z = which)
// ============================================================
__global__ __launch_bounds__(256) void transpose_half4(
    const float* __restrict__ W0, const float* __restrict__ W1,
    const float* __restrict__ W2, const float* __restrict__ W3,
    __half* __restrict__ dst)
{
    __shared__ float tile[32][33];
    const int bx = blockIdx.x, by = blockIdx.y, bz = blockIdx.z;
    const float* W = (bz == 0) ? W0 : (bz == 1) ? W1 : (bz == 2) ? W2 : W3;
    __half* out = dst + (size_t)bz * HID * HID;
    const int tx = threadIdx.x & 31, ty = threadIdx.x >> 5;
#pragma unroll
    for (int j = 0; j < 4; j++)
        tile[ty + j * 8][tx] = W[(size_t)(by * 32 + ty + j * 8) * HID + bx * 32 + tx];
    __syncthreads();
#pragma unroll
    for (int j = 0; j < 4; j++) {
        float v = tile[tx][ty + j * 8];
        out[(size_t)(bx * 32 + ty + j * 8) * HID + by * 32 + tx] = __float2half(v);
    }
}

// ============================================================
// fp16 HMMA GEMM core: CTA 128x128, BK=32, 4-stage cp.async,
// 4 warps, warp tile 64x64, fp32 accumulate.
// ============================================================
#define ROWB   80
#define TILEB  (128 * ROWB)
#define STAGEB (2 * TILEB)
#define NSTG   4
#define GEMM_SMEM (NSTG * STAGEB)   // 81920

__device__ __forceinline__ void gemm_core(const __half* __restrict__ A,
                                          const __half* __restrict__ B,
                                          float* __restrict__ C,
                                          int row0, int col0)
{
    extern __shared__ char smem[];
    const uint32_t sbase = smem_u32(smem);
    const int tid = threadIdx.x;
    const int lane = tid & 31, wid = tid >> 5;
    const int wm = wid & 1, wn = wid >> 1;

    const __half* tsrc[2] = { A + (size_t)row0 * HID, B + (size_t)col0 * HID };

    auto fill = [&](int stage, int kblk) {
        const uint32_t sb = sbase + stage * STAGEB;
        const int koff = kblk * 32;
#pragma unroll
        for (int i = 0; i < 8; i++) {
            int id = tid + i * 128;
            int t = id >> 9;
            int r = (id >> 2) & 127;
            int c = id & 3;
            cp16(sb + t * TILEB + r * ROWB + c * 16,
                 tsrc[t] + (size_t)r * HID + koff + c * 8);
        }
        cp_commit();
    };

    float acc[4][8][4];
#pragma unroll
    for (int i = 0; i < 4; i++)
#pragma unroll
        for (int j = 0; j < 8; j++)
#pragma unroll
            for (int u = 0; u < 4; u++) acc[i][j][u] = 0.f;

    fill(0, 0); fill(1, 1); fill(2, 2);

    const int a_row = (lane & 15);
    const int a_cb  = (lane >> 4) * 16;
    const int b_row = (lane & 7) + ((lane >> 4) << 3);
    const int b_cb  = ((lane >> 3) & 1) * 16;

    const int NKB = HID / 32;
    for (int c = 0; c < NKB; ++c) {
        const int s = c & 3;
        cp_wait<2>();
        __syncthreads();
        const uint32_t sb = sbase + s * STAGEB;
        const uint32_t aA = sb + (wm * 64 + a_row) * ROWB + a_cb;
        const uint32_t aB = sb + TILEB + (wn * 64 + b_row) * ROWB + b_cb;

#pragma unroll
        for (int ks = 0; ks < 2; ++ks) {
            const int kb = ks * 32;
            uint32_t a[4][4], b[4][4];
#pragma unroll
            for (int i = 0; i < 4; i++) ldm4(a[i], aA + i * (16 * ROWB) + kb);
#pragma unroll
            for (int j = 0; j < 4; j++) ldm4(b[j], aB + j * (16 * ROWB) + kb);
#pragma unroll
            for (int i = 0; i < 4; i++)
#pragma unroll
                for (int j = 0; j < 8; j++)
                    mmah(acc[i][j], a[i], &b[j >> 1][(j & 1) * 2]);
        }
        __syncthreads();
        if (c + 3 < NKB) fill((c + 3) & 3, c + 3);
        else cp_commit();
    }

    const int erow = row0 + wm * 64 + (lane >> 2);
    const int ecol = col0 + wn * 64 + (lane & 3) * 2;
#pragma unroll
    for (int i = 0; i < 4; i++)
#pragma unroll
        for (int j = 0; j < 8; j++) {
            float* p0 = C + (size_t)(erow + i * 16) * HID + ecol + j * 8;
            float* p1 = C + (size_t)(erow + i * 16 + 8) * HID + ecol + j * 8;
            *(float2*)p0 = make_float2(acc[i][j][0], acc[i][j][1]);
            *(float2*)p1 = make_float2(acc[i][j][2], acc[i][j][3]);
        }
}

// fused QKV: grid.x = 96 (32 col-blocks per weight), grid.y = 32
__global__ __launch_bounds__(128, 2) void gemm_qkv(const __half* __restrict__ A,
                                                   const __half* __restrict__ Wt,
                                                   float* __restrict__ Cq,
                                                   float* __restrict__ Ck,
                                                   float* __restrict__ Cv)
{
    const int widx = blockIdx.x >> 5;
    const int col0 = (blockIdx.x & 31) * 128;
    const int row0 = blockIdx.y * 128;
    float* C = (widx == 0) ? Cq : (widx == 1) ? Ck : Cv;
    gemm_core(A, Wt + (size_t)widx * HID * HID, C, row0, col0);
}

__global__ __launch_bounds__(128, 2) void gemm_single(const __half* __restrict__ A,
                                                      const __half* __restrict__ B,
                                                      float* __restrict__ C)
{
    gemm_core(A, B, C, blockIdx.y * 128, blockIdx.x * 128);
}

// ============================================================
// RoPE
// ============================================================
__global__ __launch_bounds__(256) void rope_kernel2(float* __restrict__ q,
                                                    float* __restrict__ k,
                                                    const int* __restrict__ pos)
{
    const int idx = blockIdx.x * 256 + threadIdx.x;
    const int j = idx & 63, t = idx >> 6;
    const double inv_freq = exp2(-(double)j * (13.287712379549449 / 64.0));
    const double ang = (double)pos[t] * inv_freq;
    const float a = (float)remainder(ang, 6.283185307179586476925286766559);
    const float c = cosf(a), s = sinf(a);
    const size_t base = (size_t)t * HID + j;
#pragma unroll 4
    for (int h = 0; h < 32; ++h) {
        const size_t o = base + h * HDD;
        float q1 = q[o], q2 = q[o + 64];
        q[o]      = q1 * c - q2 * s;
        q[o + 64] = q2 * c + q1 * s;
        float k1 = k[o], k2 = k[o + 64];
        k[o]      = k1 * c - k2 * s;
        k[o + 64] = k2 * c + k1 * s;
    }
}

// ============================================================
// KV prep: gather paged cache (or new tokens) -> contiguous
// [b][h][kv=1024][128] fp16 buffers. K split hi/lo, V single.
// ============================================================
__global__ __launch_bounds__(256) void prep_kv(
    const float* __restrict__ kcache, const float* __restrict__ vcache,
    const float* __restrict__ knew,  const float* __restrict__ vnew,
    const int* __restrict__ boff,
    __half* __restrict__ Khi, __half* __restrict__ Klo, __half* __restrict__ Vh)
{
    const int rowid = blockIdx.x * 8 + (threadIdx.x >> 5);
    const int lane = threadIdx.x & 31;
    const int p = rowid & 1023;
    const int h = (rowid >> 10) & 31;
    const int b = rowid >> 15;

    const float *ks, *vs;
    if (p < HIS) {
        int blk = boff[b * NBL + (p >> 6)];
        size_t base = (((size_t)blk * BSZ + (p & 63)) * NHD + h) * HDD;
        ks = kcache + base; vs = vcache + base;
    } else {
        size_t base = ((size_t)(b * QL + p - HIS)) * HID + h * HDD;
        ks = knew + base; vs = vnew + base;
    }
    float4 kv = *(const float4*)(ks + lane * 4);
    float4 vv = *(const float4*)(vs + lane * 4);

    __half khx = __float2half(kv.x), khy = __float2half(kv.y);
    __half khz = __float2half(kv.z), khw = __float2half(kv.w);
    __half klx = __float2half(kv.x - __half2float(khx));
    __half kly = __float2half(kv.y - __half2float(khy));
    __half klz = __float2half(kv.z - __half2float(khz));
    __half klw = __float2half(kv.w - __half2float(khw));

    const size_t o = (size_t)rowid * HDD + lane * 4;
    *(__half2*)(Khi + o)     = __half2(khx, khy);
    *(__half2*)(Khi + o + 2) = __half2(khz, khw);
    *(__half2*)(Klo + o)     = __half2(klx, kly);
    *(__half2*)(Klo + o + 2) = __half2(klz, klw);
    *(__half2*)(Vh + o)      = __floats2half2_rn(vv.x, vv.y);
    *(__half2*)(Vh + o + 2)  = __floats2half2_rn(vv.z, vv.w);
}

// ============================================================
// HMMA flash attention. Grid (qt=4, h=32, b=8), 256 threads.
// Q tile 128x128, KV tile 64, 2-stage cp.async. Output fp16.
// ============================================================
#define AS 136
#define QLO_OFF (128 * AS)
#define KV_BASE (2 * 128 * AS)
#define KV_STG  (3 * 64 * AS)
#define ATT_SMEM ((KV_BASE + 2 * KV_STG) * 2)   // 174080 bytes

__global__ __launch_bounds__(256, 1) void attn_mma(
    const float* __restrict__ qbuf,
    const __half* __restrict__ Khi, const __half* __restrict__ Klo,
    const __half* __restrict__ Vh, __half* __restrict__ obuf)
{
    extern __shared__ __half hsm[];
    const int qt = blockIdx.x, h = blockIdx.y, b = blockIdx.z;
    const int tid = threadIdx.x;
    const int lane = tid & 31, w = tid >> 5;
    const float scale = 0.08838834764831845f;

    {
        const int r = tid >> 1, cb = (tid & 1) * 64;
        const float* src = qbuf + (size_t)(b * QL + qt * 128 + r) * HID + h * HDD + cb;
        __half* dh = hsm + r * AS + cb;
        __half* dl = dh + QLO_OFF;
#pragma unroll
        for (int i = 0; i < 16; i++) {
            float4 v = *(const float4*)(src + i * 4);
            v.x *= scale; v.y *= scale; v.z *= scale; v.w *= scale;
            __half hx = __float2half(v.x), hy = __float2half(v.y);
            __half hz = __float2half(v.z), hw = __float2half(v.w);
            dh[i*4+0] = hx; dh[i*4+1] = hy; dh[i*4+2] = hz; dh[i*4+3] = hw;
            dl[i*4+0] = __float2half(v.x - __half2float(hx));
            dl[i*4+1] = __float2half(v.y - __half2float(hy));
            dl[i*4+2] = __float2half(v.z - __half2float(hz));
            dl[i*4+3] = __float2half(v.w - __half2float(hw));
        }
    }

    const size_t kvoff = ((size_t)(b * NHD + h)) * 1024 * HDD;
    const __half* kp[3] = { Khi + kvoff, Klo + kvoff, Vh + kvoff };
    const uint32_t sb = smem_u32(hsm);

    auto fill = [&](int stage, int kt) {
#pragma unroll
        for (int i = 0; i < 12; i++) {
            int id = tid + i * 256;
            int buf = id >> 10;
            int r = (id >> 4) & 63;
            int c = id & 15;
            uint32_t dst = sb + (uint32_t)(KV_BASE + stage * KV_STG + buf * (64 * AS) + r * AS + c * 8) * 2;
            cp16(dst, kp[buf] + (size_t)(kt * 64 + r) * HDD + c * 8);
        }
        cp_commit();
    };

    float m0 = -1e30f, m1 = -1e30f, l0 = 0.f, l1 = 0.f;
    float o[16][4];
#pragma unroll
    for (int d = 0; d < 16; d++)
#pragma unroll
        for (int u = 0; u < 4; u++) o[d][u] = 0.f;

    const int r0 = lane >> 2;
    const int qp0 = HIS + qt * 128 + w * 16 + r0;
    const int qp1 = qp0 + 8;

    const uint32_t aQh = sb + ((w * 16 + (lane & 15)) * AS + (lane >> 4) * 8) * 2;
    const uint32_t aQl = aQh + QLO_OFF * 2;
    const uint32_t aKrow = (lane & 7) + ((lane >> 4) << 3);
    const uint32_t aKcb  = ((lane >> 3) & 1) * 8;
    const uint32_t aVrow = (lane & 7) + ((lane >> 3) & 1) * 8;
    const uint32_t aVcb  = (lane >> 4) * 8;

    const int ntiles = 10 + 2 * qt;
    fill(0, 0); fill(1, 1);

    for (int kt = 0; kt < ntiles; kt++) {
        const int s = kt & 1;
        cp_wait<1>();
        __syncthreads();
        const uint32_t kbs = sb + (uint32_t)(KV_BASE + s * KV_STG) * 2;
        const uint32_t vbs = kbs + (uint32_t)(2 * 64 * AS) * 2;

        float S[8][4];
#pragma unroll
        for (int f = 0; f < 8; f++)
#pragma unroll
            for (int u = 0; u < 4; u++) S[f][u] = 0.f;

#pragma unroll
        for (int kc = 0; kc < 8; kc++) {
            uint32_t qh[4], ql[4];
            ldm4(qh, aQh + kc * 32);
            ldm4(ql, aQl + kc * 32);
#pragma unroll
            for (int jp = 0; jp < 4; jp++) {
                uint32_t kh[4], kl[4];
                const uint32_t ka = kbs + ((jp * 16 + aKrow) * AS + aKcb + kc * 16) * 2;
                ldm4(kh, ka);
                ldm4(kl, ka + (uint32_t)(64 * AS) * 2);
                mmah(S[2*jp],   qh, &kh[0]);
                mmah(S[2*jp],   qh, &kl[0]);
                mmah(S[2*jp],   ql, &kh[0]);
                mmah(S[2*jp+1], qh, &kh[2]);
                mmah(S[2*jp+1], qh, &kl[2]);
                mmah(S[2*jp+1], ql, &kh[2]);
            }
        }

        if (kt >= ntiles - 2) {
#pragma unroll
            for (int f = 0; f < 8; f++) {
                int c0 = kt * 64 + f * 8 + (lane & 3) * 2;
                if (c0     > qp0) S[f][0] = -1e30f;
                if (c0 + 1 > qp0) S[f][1] = -1e30f;
                if (c0     > qp1) S[f][2] = -1e30f;
                if (c0 + 1 > qp1) S[f][3] = -1e30f;
            }
        }

        float tm0 = -1e30f, tm1 = -1e30f;
#pragma unroll
        for (int f = 0; f < 8; f++) {
            tm0 = fmaxf(tm0, fmaxf(S[f][0], S[f][1]));
            tm1 = fmaxf(tm1, fmaxf(S[f][2], S[f][3]));
        }
        tm0 = fmaxf(tm0, __shfl_xor_sync(0xffffffffu, tm0, 1));
        tm0 = fmaxf(tm0, __shfl_xor_sync(0xffffffffu, tm0, 2));
        tm1 = fmaxf(tm1, __shfl_xor_sync(0xffffffffu, tm1, 1));
        tm1 = fmaxf(tm1, __shfl_xor_sync(0xffffffffu, tm1, 2));
        const float mn0 = fmaxf(m0, tm0), mn1 = fmaxf(m1, tm1);
        const float al0 = fexp(m0 - mn0), al1 = fexp(m1 - mn1);

        float s0 = 0.f, s1 = 0.f;
#pragma unroll
        for (int f = 0; f < 8; f++) {
            S[f][0] = fexp(S[f][0] - mn0);
            S[f][1] = fexp(S[f][1] - mn0);
            S[f][2] = fexp(S[f][2] - mn1);
            S[f][3] = fexp(S[f][3] - mn1);
            s0 += S[f][0] + S[f][1];
            s1 += S[f][2] + S[f][3];
        }
        s0 += __shfl_xor_sync(0xffffffffu, s0, 1);
        s0 += __shfl_xor_sync(0xffffffffu, s0, 2);
        s1 += __shfl_xor_sync(0xffffffffu, s1, 1);
        s1 += __shfl_xor_sync(0xffffffffu, s1, 2);
        l0 = l0 * al0 + s0;
        l1 = l1 * al1 + s1;
        m0 = mn0; m1 = mn1;

#pragma unroll
        for (int d = 0; d < 16; d++) {
            o[d][0] *= al0; o[d][1] *= al0;
            o[d][2] *= al1; o[d][3] *= al1;
        }

        uint32_t pa[4][4];
#pragma unroll
        for (int kk = 0; kk < 4; kk++) {
            pa[kk][0] = packh2(S[2*kk][0],   S[2*kk][1]);
            pa[kk][1] = packh2(S[2*kk][2],   S[2*kk][3]);
            pa[kk][2] = packh2(S[2*kk+1][0], S[2*kk+1][1]);
            pa[kk][3] = packh2(S[2*kk+1][2], S[2*kk+1][3]);
        }

#pragma unroll
        for (int kk = 0; kk < 4; kk++) {
#pragma unroll
            for (int dg = 0; dg < 8; dg++) {
                uint32_t bv[4];
                ldm4t(bv, vbs + ((kk * 16 + aVrow) * AS + dg * 16 + aVcb) * 2);
                mmah(o[dg*2],   pa[kk], &bv[0]);
                mmah(o[dg*2+1], pa[kk], &bv[2]);
            }
        }

        __syncthreads();
        if (kt + 2 < ntiles) fill(s, kt + 2);
        else cp_commit();
    }

    const float inv0 = 1.f / l0, inv1 = 1.f / l1;
    const int gr0 = b * QL + qt * 128 + w * 16 + r0;
    const int gr1 = gr0 + 8;
    const int col = h * HDD + (lane & 3) * 2;
#pragma unroll
    for (int d = 0; d < 16; d++) {
        *(__half2*)(obuf + (size_t)gr0 * HID + col + d * 8) = __floats2half2_rn(o[d][0] * inv0, o[d][1] * inv0);
        *(__half2*)(obuf + (size_t)gr1 * HID + col + d * 8) = __floats2half2_rn(o[d][2] * inv1, o[d][3] * inv1);
    }
}

// ============================================================
// launch
// ============================================================
extern "C" void kernel_launch(void* const* d_in, const int* in_sizes, int n_in,
                              void* d_out, int out_size)
{
    const float* hidden = (const float*)d_in[0];
    const float* Wq     = (const float*)d_in[1];
    const float* Wk     = (const float*)d_in[2];
    const float* Wv     = (const float*)d_in[3];
    const float* Wo     = (const float*)d_in[4];
    const float* kcache = (const float*)d_in[5];
    const float* vcache = (const float*)d_in[6];
    const int*   boff   = (const int*)d_in[7];
    const int*   pos    = (const int*)d_in[8];
    float* out = (float*)d_out;

    float *gq, *gk, *gv;
    __half *ah, *wt, *khi, *klo, *vh;
    cudaGetSymbolAddress((void**)&gq, g_q);
    cudaGetSymbolAddress((void**)&gk, g_k);
    cudaGetSymbolAddress((void**)&gv, g_v);
    cudaGetSymbolAddress((void**)&ah, g_Ah);
    cudaGetSymbolAddress((void**)&wt, g_Wt);
    cudaGetSymbolAddress((void**)&khi, g_Khi);
    cudaGetSymbolAddress((void**)&klo, g_Klo);
    cudaGetSymbolAddress((void**)&vh, g_Vh);

    cudaFuncSetAttribute(gemm_qkv, cudaFuncAttributeMaxDynamicSharedMemorySize, GEMM_SMEM);
    cudaFuncSetAttribute(gemm_single, cudaFuncAttributeMaxDynamicSharedMemorySize, GEMM_SMEM);
    cudaFuncSetAttribute(attn_mma, cudaFuncAttributeMaxDynamicSharedMemorySize, ATT_SMEM);

    const int ncvt = TOK * HID / 4 / 256;
    dim3 tgrid(HID / 32, HID / 32, 4);

    cvt_half<<<ncvt, 256>>>((const float4*)hidden, ah);
    transpose_half4<<<tgrid, 256>>>(Wq, Wk, Wv, Wo, wt);

    dim3 qkvgrid(3 * HID / 128, TOK / 128);
    gemm_qkv<<<qkvgrid, 128, GEMM_SMEM>>>(ah, wt, gq, gk, gv);

    rope_kernel2<<<TOK * 64 / 256, 256>>>(gq, gk, pos);

    prep_kv<<<NB * NHD * 1024 / 8, 256>>>(kcache, vcache, gk, gv, boff, khi, klo, vh);

    dim3 ag(QL / 128, NHD, NB);
    attn_mma<<<ag, 256, ATT_SMEM>>>(gq, khi, klo, vh, ah);

    dim3 ogrid(HID / 128, TOK / 128);
    gemm_single<<<ogrid, 128, GEMM_SMEM>>>(ah, wt + 3 * (size_t)HID * HID, out);
}